// round 9
// baseline (speedup 1.0000x reference)
#include <cuda_runtime.h>
#include <cuda_bf16.h>
#include <math.h>
#include <stdint.h>

#define DIM 256
#define HEADS 8
#define WIN 64
#define N1 128
#define NWIN 2048
#define SCALE 0.17677669529663687f

// ---------------- device scratch (fragment-packed) ----------------
__device__ uint4 g_q4h[8 * 8 * 2 * 32];          // [h][qb][ks][lane]
__device__ uint4 g_q4l[8 * 8 * 2 * 32];
__device__ float4 g_b4[8 * 8 * 8 * 32];          // [h][qb][j][lane]
__device__ uint4 g_kvw4[16 * 4 * 512];           // [kcg][t][n]
__device__ uint4 g_pw4[16 * 4 * 256];            // [kc][t][n]

// ---------------- helpers ----------------
__device__ __forceinline__ uint32_t pack2(float x0, float x1, uint32_t& lo) {
    __nv_bfloat16 h0 = __float2bfloat16(x0);
    __nv_bfloat16 h1 = __float2bfloat16(x1);
    __nv_bfloat16 l0 = __float2bfloat16(x0 - __bfloat162float(h0));
    __nv_bfloat16 l1 = __float2bfloat16(x1 - __bfloat162float(h1));
    lo = ((uint32_t)__bfloat16_as_ushort(l1) << 16) | (uint32_t)__bfloat16_as_ushort(l0);
    return ((uint32_t)__bfloat16_as_ushort(h1) << 16) | (uint32_t)__bfloat16_as_ushort(h0);
}

__device__ __forceinline__ void mma16(float c[4], uint32_t a0, uint32_t a1,
                                      uint32_t a2, uint32_t a3,
                                      uint32_t b0, uint32_t b1) {
    asm volatile(
        "mma.sync.aligned.m16n8k16.row.col.f32.bf16.bf16.f32 "
        "{%0,%1,%2,%3},{%4,%5,%6,%7},{%8,%9},{%0,%1,%2,%3};\n"
        : "+f"(c[0]), "+f"(c[1]), "+f"(c[2]), "+f"(c[3])
        : "r"(a0), "r"(a1), "r"(a2), "r"(a3), "r"(b0), "r"(b1));
}
__device__ __forceinline__ void mma3(float c[4], const uint4& ah, const uint4& al,
                                     const uint4& B) {
    mma16(c, ah.x, ah.y, ah.z, ah.w, B.x, B.y);
    mma16(c, ah.x, ah.y, ah.z, ah.w, B.z, B.w);
    mma16(c, al.x, al.y, al.z, al.w, B.x, B.y);
}

// bias formula (relative position)
__device__ __forceinline__ float bias_val(const float* rpb, int h, int r, int k) {
    int i1 = r >> 3, j1 = r & 7, i2 = k >> 3, j2 = k & 7;
    int idx = (i1 - i2 + 7) * 15 + (j1 - j2 + 7);
    return rpb[idx * HEADS + h];
}

// ---------------- prep kernels ----------------
__global__ void prep_q4(const float* __restrict__ e) {
    int i = blockIdx.x * blockDim.x + threadIdx.x;
    if (i >= 4096) return;
    int lane = i & 31, ks = (i >> 5) & 1, qb = (i >> 6) & 7, h = i >> 9;
    int g = lane >> 2, t = lane & 3;
    int q0 = qb * 16 + g;
    uint4 hi, lo;
    int d0 = h * 32 + (8 * ks + t) * 2;
    int d1 = h * 32 + (8 * ks + t + 4) * 2;
    hi.x = pack2(e[q0 * DIM + d0] * SCALE, e[q0 * DIM + d0 + 1] * SCALE, lo.x);
    hi.y = pack2(e[(q0 + 8) * DIM + d0] * SCALE, e[(q0 + 8) * DIM + d0 + 1] * SCALE, lo.y);
    hi.z = pack2(e[q0 * DIM + d1] * SCALE, e[q0 * DIM + d1 + 1] * SCALE, lo.z);
    hi.w = pack2(e[(q0 + 8) * DIM + d1] * SCALE, e[(q0 + 8) * DIM + d1 + 1] * SCALE, lo.w);
    g_q4h[i] = hi; g_q4l[i] = lo;
}

__global__ void prep_b4(const float* __restrict__ rpb) {
    int i = blockIdx.x * blockDim.x + threadIdx.x;
    if (i >= 16384) return;
    int lane = i & 31, j = (i >> 5) & 7, qb = (i >> 8) & 7, h = i >> 11;
    int g = lane >> 2, t = lane & 3;
    int r0 = (qb * 16 + g) & 63, r1 = (qb * 16 + g + 8) & 63;
    int c = 8 * j + 2 * t;
    float4 v;
    v.x = bias_val(rpb, h, r0, c);
    v.y = bias_val(rpb, h, r0, c + 1);
    v.z = bias_val(rpb, h, r1, c);
    v.w = bias_val(rpb, h, r1, c + 1);
    g_b4[i] = v;
}

__global__ void prep_w4(const float* __restrict__ kvw, const float* __restrict__ pw) {
    int i = blockIdx.x * blockDim.x + threadIdx.x;
    if (i < 32768) {
        int n = i & 511, t = (i >> 9) & 3, kcg = i >> 11;   // 0..15
        int kwA = kcg * 8 + t, kwB = kwA + 4;
        uint4 v;
        v.x = pack2(kvw[n * 256 + 2 * kwA], kvw[n * 256 + 2 * kwA + 1], v.z);
        v.y = pack2(kvw[n * 256 + 2 * kwB], kvw[n * 256 + 2 * kwB + 1], v.w);
        g_kvw4[i] = v;
    } else if (i < 49152) {
        int ii = i - 32768;
        int n = ii & 255, t = (ii >> 8) & 3, kc = ii >> 10;  // 0..15
        int kwA = kc * 8 + t, kwB = kwA + 4;
        uint4 v;
        v.x = pack2(pw[n * 256 + 2 * kwA], pw[n * 256 + 2 * kwA + 1], v.z);
        v.y = pack2(pw[n * 256 + 2 * kwB], pw[n * 256 + 2 * kwB + 1], v.w);
        g_pw4[ii] = v;
    }
}

// ---------------- fused window kernel (KV GEMM + attention + proj) -----------
// smem (uint4 units):
//  a4  @ 0      size 4352  (hi [kcg*136 + t*34 + m*8 + g], lo +2176)
//                phase2: V [ks*1024 + d*4 + tq];  phase3: O/A [kc*520+t*130+qb*16+plane*8+g]
//  k4  @ 4352   size 4352  [key*68 + G*4 + t]     (phase3: part of O/A)
//  kvb @ uint4 8704 (512 floats)
// total 8832 uint4 = 141312 bytes
#define A4_OFF  0
#define K4_OFF  4352
#define SMEM_BYTES 141312

extern __shared__ uint4 sm4[];

__global__ __launch_bounds__(512, 1)
void win_attn(const float* __restrict__ x, const float* __restrict__ kvb,
              const float* __restrict__ pb, float* __restrict__ out) {
    const int tid  = threadIdx.x;
    const int bw   = blockIdx.x;
    const int b    = bw >> 10;
    const int wr   = (bw >> 5) & 31;
    const int wc   = bw & 31;
    const int w    = tid >> 5;
    const int lane = tid & 31;
    const int g    = lane >> 2;
    const int t    = lane & 3;
    float* kvbf = (float*)(sm4 + 8704);
    uint32_t* a4w = (uint32_t*)sm4;

    // ---- load window tile, split+pack, scatter into a4 fragment layout ----
    {
        const float4* xv = (const float4*)(x +
            ((size_t)((b * 256 + wr * 8) * 256 + wc * 8)) * 256);
        #pragma unroll
        for (int i = 0; i < 8; i++) {
            int idx = tid + i * 512;
            int tok = idx >> 6, c4 = idx & 63;
            int r = tok >> 3, cc = tok & 7;
            float4 v = xv[r * 16384 + cc * 64 + c4];
            int m = tok >> 4, gg = tok & 15;
            int g2 = gg & 7, r8 = gg >> 3;
            int kcg = c4 >> 2, rem = c4 & 3;
            uint32_t lo0, lo1;
            uint32_t hi0 = pack2(v.x, v.y, lo0);
            uint32_t hi1 = pack2(v.z, v.w, lo1);
            int tt0 = 2 * rem, tt1 = tt0 + 1;
            int i0 = kcg * 136 + (tt0 & 3) * 34 + m * 8 + g2;
            int w0 = r8 + 2 * (tt0 >> 2);
            a4w[i0 * 4 + w0] = hi0;
            a4w[(i0 + 2176) * 4 + w0] = lo0;
            int i1 = kcg * 136 + (tt1 & 3) * 34 + m * 8 + g2;
            int w1 = r8 + 2 * (tt1 >> 2);
            a4w[i1 * 4 + w1] = hi1;
            a4w[(i1 + 2176) * 4 + w1] = lo1;
        }
        kvbf[tid] = kvb[tid];
    }
    __syncthreads();

    // ---- KV GEMM: B operands streamed straight from L2 (no staging) ----
    const int wmK = (w >> 3) * 32;
    const int wnK = (w & 7) * 64;
    const int mB  = (w >> 3) * 2;

    float acc[2][8][4];
    #pragma unroll
    for (int mt = 0; mt < 2; mt++)
        #pragma unroll
        for (int j = 0; j < 8; j++)
            #pragma unroll
            for (int e = 0; e < 4; e++) acc[mt][j][e] = 0.f;

    #pragma unroll
    for (int kcg = 0; kcg < 16; kcg++) {
        uint4 Ah[2], Al[2];
        #pragma unroll
        for (int mt = 0; mt < 2; mt++) {
            int ai = A4_OFF + kcg * 136 + t * 34 + (mB + mt) * 8 + g;
            Ah[mt] = sm4[ai];
            Al[mt] = sm4[ai + 2176];
        }
        #pragma unroll
        for (int j = 0; j < 8; j++) {
            uint4 B = __ldg(&g_kvw4[kcg * 2048 + t * 512 + wnK + 8 * j + g]);
            mma3(acc[0][j], Ah[0], Al[0], B);
            mma3(acc[1][j], Ah[1], Al[1], B);
        }
    }
    __syncthreads();   // all a4 reads done (V will alias a4)

    // ---- epilogues: K warps (wnK<256) -> k4 ; V warps -> a4 alias ----
    if (wnK < 256) {
        #pragma unroll
        for (int mt = 0; mt < 2; mt++) {
            int key0 = wmK + mt * 16 + g;
            #pragma unroll
            for (int jp = 0; jp < 4; jp++) {
                int j = 2 * jp;
                int c  = wnK + 8 * j + 2 * t;
                int c2 = c + 8;
                float b0 = kvbf[c], b1 = kvbf[c + 1];
                float b2 = kvbf[c2], b3 = kvbf[c2 + 1];
                int G = (wnK >> 4) + jp;
                uint4 u;
                u.x = pack2(acc[mt][j][0] + b0, acc[mt][j][1] + b1, u.z);
                u.y = pack2(acc[mt][j + 1][0] + b2, acc[mt][j + 1][1] + b3, u.w);
                sm4[K4_OFF + key0 * 68 + G * 4 + t] = u;
                uint4 v;
                v.x = pack2(acc[mt][j][2] + b0, acc[mt][j][3] + b1, v.z);
                v.y = pack2(acc[mt][j + 1][2] + b2, acc[mt][j + 1][3] + b3, v.w);
                sm4[K4_OFF + (key0 + 8) * 68 + G * 4 + t] = v;
            }
        }
    } else {
        #pragma unroll
        for (int mt = 0; mt < 2; mt++) {
            int ks = mB + mt;
            #pragma unroll
            for (int j = 0; j < 8; j++) {
                int c = wnK - 256 + 8 * j + 2 * t;
                float b0 = kvbf[256 + c], b1 = kvbf[256 + c + 1];
                float v0 = acc[mt][j][0] + b0, v1 = acc[mt][j][1] + b1;
                float v2 = acc[mt][j][2] + b0, v3 = acc[mt][j][3] + b1;
                float o0 = __shfl_xor_sync(0xffffffffu, v0, 4);
                float o1 = __shfl_xor_sync(0xffffffffu, v1, 4);
                float o2 = __shfl_xor_sync(0xffffffffu, v2, 4);
                float o3 = __shfl_xor_sync(0xffffffffu, v3, 4);
                if ((g & 1) == 0) {
                    int tq = g >> 1;
                    uint4 u;
                    u.x = pack2(v0, o0, u.z);
                    u.y = pack2(v2, o2, u.w);
                    sm4[A4_OFF + ks * 1024 + c * 4 + tq] = u;
                    uint4 v;
                    v.x = pack2(v1, o1, v.z);
                    v.y = pack2(v3, o3, v.w);
                    sm4[A4_OFF + ks * 1024 + (c + 1) * 4 + tq] = v;
                }
            }
        }
    }
    __syncthreads();

    // ---- attention: 16 warps = 8 q-blocks x 2 head-groups; O kept in regs ----
    const int qb = w >> 1;
    const int hbase = (w & 1) * 4;
    uint32_t Ohi[4][8], Olo[4][8];

    #pragma unroll
    for (int hh = 0; hh < 4; hh++) {
        const int h = hbase + hh;

        float sacc[8][4];
        #pragma unroll
        for (int j = 0; j < 8; j++) {
            float4 bv = __ldg(&g_b4[((h * 8 + qb) * 8 + j) * 32 + lane]);
            sacc[j][0] = bv.x; sacc[j][1] = bv.y;
            sacc[j][2] = bv.z; sacc[j][3] = bv.w;
        }
        #pragma unroll
        for (int ks = 0; ks < 2; ks++) {
            uint4 Qh = __ldg(&g_q4h[((h * 8 + qb) * 2 + ks) * 32 + lane]);
            uint4 Ql = __ldg(&g_q4l[((h * 8 + qb) * 2 + ks) * 32 + lane]);
            #pragma unroll
            for (int j = 0; j < 8; j++) {
                uint4 K = sm4[K4_OFF + (8 * j + g) * 68 + (h * 2 + ks) * 4 + t];
                mma3(sacc[j], Qh, Ql, K);
            }
        }

        // softmax over 64 keys (rows in 4-lane groups)
        float m0 = -1e30f, m1 = -1e30f;
        #pragma unroll
        for (int j = 0; j < 8; j++) {
            m0 = fmaxf(m0, fmaxf(sacc[j][0], sacc[j][1]));
            m1 = fmaxf(m1, fmaxf(sacc[j][2], sacc[j][3]));
        }
        m0 = fmaxf(m0, __shfl_xor_sync(0xffffffffu, m0, 1));
        m0 = fmaxf(m0, __shfl_xor_sync(0xffffffffu, m0, 2));
        m1 = fmaxf(m1, __shfl_xor_sync(0xffffffffu, m1, 1));
        m1 = fmaxf(m1, __shfl_xor_sync(0xffffffffu, m1, 2));
        float s0 = 0.f, s1 = 0.f;
        #pragma unroll
        for (int j = 0; j < 8; j++) {
            sacc[j][0] = __expf(sacc[j][0] - m0); s0 += sacc[j][0];
            sacc[j][1] = __expf(sacc[j][1] - m0); s0 += sacc[j][1];
            sacc[j][2] = __expf(sacc[j][2] - m1); s1 += sacc[j][2];
            sacc[j][3] = __expf(sacc[j][3] - m1); s1 += sacc[j][3];
        }
        s0 += __shfl_xor_sync(0xffffffffu, s0, 1);
        s0 += __shfl_xor_sync(0xffffffffu, s0, 2);
        s1 += __shfl_xor_sync(0xffffffffu, s1, 1);
        s1 += __shfl_xor_sync(0xffffffffu, s1, 2);
        float inv0 = 1.0f / s0, inv1 = 1.0f / s1;
        #pragma unroll
        for (int j = 0; j < 8; j++) {
            sacc[j][0] *= inv0; sacc[j][1] *= inv0;
            sacc[j][2] *= inv1; sacc[j][3] *= inv1;
        }

        // O = P V (A-fragments repacked from sacc in registers)
        float oacc[4][4];
        #pragma unroll
        for (int j = 0; j < 4; j++)
            #pragma unroll
            for (int e = 0; e < 4; e++) oacc[j][e] = 0.f;

        #pragma unroll
        for (int ks = 0; ks < 4; ks++) {
            uint4 ah, al;
            ah.x = pack2(sacc[2 * ks][0], sacc[2 * ks][1], al.x);
            ah.y = pack2(sacc[2 * ks][2], sacc[2 * ks][3], al.y);
            ah.z = pack2(sacc[2 * ks + 1][0], sacc[2 * ks + 1][1], al.z);
            ah.w = pack2(sacc[2 * ks + 1][2], sacc[2 * ks + 1][3], al.w);
            #pragma unroll
            for (int j = 0; j < 4; j++) {
                uint4 V = sm4[A4_OFF + ks * 1024 + (h * 32 + 8 * j + g) * 4 + t];
                mma3(oacc[j], ah, al, V);
            }
        }

        // pack O into registers (retained across heads)
        #pragma unroll
        for (int jp = 0; jp < 2; jp++) {
            int j = 2 * jp;
            Ohi[hh][jp * 4 + 0] = pack2(oacc[j][0], oacc[j][1], Olo[hh][jp * 4 + 0]);
            Ohi[hh][jp * 4 + 1] = pack2(oacc[j][2], oacc[j][3], Olo[hh][jp * 4 + 1]);
            Ohi[hh][jp * 4 + 2] = pack2(oacc[j + 1][0], oacc[j + 1][1], Olo[hh][jp * 4 + 2]);
            Ohi[hh][jp * 4 + 3] = pack2(oacc[j + 1][2], oacc[j + 1][3], Olo[hh][jp * 4 + 3]);
        }
    }
    __syncthreads();   // all K/V smem reads complete

    // ---- write O fragments into smem A region (a4+k4 reused) ----
    #pragma unroll
    for (int hh = 0; hh < 4; hh++) {
        #pragma unroll
        for (int jp = 0; jp < 2; jp++) {
            int kc = (hbase + hh) * 2 + jp;
            int base = kc * 520 + t * 130 + qb * 16;
            sm4[base + g] = make_uint4(Ohi[hh][jp * 4 + 0], Ohi[hh][jp * 4 + 1],
                                       Ohi[hh][jp * 4 + 2], Ohi[hh][jp * 4 + 3]);
            sm4[base + 8 + g] = make_uint4(Olo[hh][jp * 4 + 0], Olo[hh][jp * 4 + 1],
                                           Olo[hh][jp * 4 + 2], Olo[hh][jp * 4 + 3]);
        }
    }
    __syncthreads();   // O fragments visible

    // ---- proj phase: out = O @ pw^T + pb ; B streamed from L2 ----
    const int wmP = (w >> 2) * 32;
    const int wnP = (w & 3) * 64;
    const int qB  = (w >> 2) * 2;

    float pacc[2][8][4];
    #pragma unroll
    for (int mt = 0; mt < 2; mt++)
        #pragma unroll
        for (int j = 0; j < 8; j++)
            #pragma unroll
            for (int e = 0; e < 4; e++) pacc[mt][j][e] = 0.f;

    #pragma unroll
    for (int kc = 0; kc < 16; kc++) {
        uint4 Ah[2], Al[2];
        #pragma unroll
        for (int mt = 0; mt < 2; mt++) {
            int ai = kc * 520 + t * 130 + (qB + mt) * 16;
            Ah[mt] = sm4[ai + g];
            Al[mt] = sm4[ai + 8 + g];
        }
        #pragma unroll
        for (int j = 0; j < 8; j++) {
            uint4 B = __ldg(&g_pw4[kc * 1024 + t * 256 + wnP + 8 * j + g]);
            mma3(pacc[0][j], Ah[0], Al[0], B);
            mma3(pacc[1][j], Ah[1], Al[1], B);
        }
    }

    // epilogue
    #pragma unroll
    for (int j = 0; j < 8; j++) {
        int oc = wnP + 8 * j + 2 * t;
        float b0 = __ldg(pb + oc), b1 = __ldg(pb + oc + 1);
        #pragma unroll
        for (int mt = 0; mt < 2; mt++) {
            size_t r = (size_t)bw * 128 + wmP + mt * 16 + g;
            *(float2*)(out + r * 256 + oc) =
                make_float2(pacc[mt][j][0] + b0, pacc[mt][j][1] + b1);
            *(float2*)(out + (r + 8) * 256 + oc) =
                make_float2(pacc[mt][j][2] + b0, pacc[mt][j][3] + b1);
        }
    }
}

// ---------------- launch ----------------
static const float* find_by_size(void* const* d_in, const int* in_sizes,
                                 int n_in, int want) {
    for (int i = 0; i < n_in; i++)
        if (in_sizes[i] == want) return (const float*)d_in[i];
    return nullptr;
}

extern "C" void kernel_launch(void* const* d_in, const int* in_sizes, int n_in,
                              void* d_out, int out_size) {
    const float* embeds = find_by_size(d_in, in_sizes, n_in, 128 * 256);
    const float* x      = find_by_size(d_in, in_sizes, n_in, 2 * 256 * 256 * 256);
    const float* rpb    = find_by_size(d_in, in_sizes, n_in, 225 * 8);
    const float* kvw    = find_by_size(d_in, in_sizes, n_in, 512 * 256);
    const float* kvb    = find_by_size(d_in, in_sizes, n_in, 512);
    const float* pw     = find_by_size(d_in, in_sizes, n_in, 256 * 256);
    const float* pb     = find_by_size(d_in, in_sizes, n_in, 256);
    float* out = (float*)d_out;

    prep_q4<<<16, 256>>>(embeds);
    prep_b4<<<64, 256>>>(rpb);
    prep_w4<<<192, 256>>>(kvw, pw);

    cudaFuncSetAttribute(win_attn,
                         cudaFuncAttributeMaxDynamicSharedMemorySize, SMEM_BYTES);
    win_attn<<<NWIN, 512, SMEM_BYTES>>>(x, kvb, pb, out);
}

// round 11
// speedup vs baseline: 1.0893x; 1.0893x over previous
#include <cuda_runtime.h>
#include <cuda_bf16.h>
#include <math.h>
#include <stdint.h>

#define DIM 256
#define HEADS 8
#define WIN 64
#define N1 128
#define NWIN 2048
#define SCALE 0.17677669529663687f

// ---------------- device scratch (fragment-packed) ----------------
__device__ uint4 g_q4h[8 * 8 * 2 * 32];          // [h][qb][ks][lane]
__device__ uint4 g_q4l[8 * 8 * 2 * 32];
__device__ float4 g_b4[8 * 8 * 8 * 32];          // [h][qb][j][lane]
__device__ uint4 g_kvw4[16 * 4 * 512];           // [kcg][t][n]
__device__ uint4 g_pw4[16 * 4 * 256];            // [kc][t][n]

// ---------------- helpers ----------------
__device__ __forceinline__ uint32_t pack2(float x0, float x1, uint32_t& lo) {
    __nv_bfloat16 h0 = __float2bfloat16(x0);
    __nv_bfloat16 h1 = __float2bfloat16(x1);
    __nv_bfloat16 l0 = __float2bfloat16(x0 - __bfloat162float(h0));
    __nv_bfloat16 l1 = __float2bfloat16(x1 - __bfloat162float(h1));
    lo = ((uint32_t)__bfloat16_as_ushort(l1) << 16) | (uint32_t)__bfloat16_as_ushort(l0);
    return ((uint32_t)__bfloat16_as_ushort(h1) << 16) | (uint32_t)__bfloat16_as_ushort(h0);
}

__device__ __forceinline__ void mma16(float c[4], uint32_t a0, uint32_t a1,
                                      uint32_t a2, uint32_t a3,
                                      uint32_t b0, uint32_t b1) {
    asm volatile(
        "mma.sync.aligned.m16n8k16.row.col.f32.bf16.bf16.f32 "
        "{%0,%1,%2,%3},{%4,%5,%6,%7},{%8,%9},{%0,%1,%2,%3};\n"
        : "+f"(c[0]), "+f"(c[1]), "+f"(c[2]), "+f"(c[3])
        : "r"(a0), "r"(a1), "r"(a2), "r"(a3), "r"(b0), "r"(b1));
}
__device__ __forceinline__ void mma3(float c[4], const uint4& ah, const uint4& al,
                                     const uint4& B) {
    mma16(c, ah.x, ah.y, ah.z, ah.w, B.x, B.y);
    mma16(c, ah.x, ah.y, ah.z, ah.w, B.z, B.w);
    mma16(c, al.x, al.y, al.z, al.w, B.x, B.y);
}

__device__ __forceinline__ void cp16(uint32_t dst_smem, const void* src) {
    asm volatile("cp.async.cg.shared.global [%0], [%1], 16;\n"
                 :: "r"(dst_smem), "l"(src));
}
#define CP_COMMIT() asm volatile("cp.async.commit_group;\n")
#define CP_WAIT0()  asm volatile("cp.async.wait_group 0;\n")

// bias formula (relative position)
__device__ __forceinline__ float bias_val(const float* rpb, int h, int r, int k) {
    int i1 = r >> 3, j1 = r & 7, i2 = k >> 3, j2 = k & 7;
    int idx = (i1 - i2 + 7) * 15 + (j1 - j2 + 7);
    return rpb[idx * HEADS + h];
}

// ---------------- merged prep kernel ----------------
__global__ void prep_all(const float* __restrict__ e, const float* __restrict__ rpb,
                         const float* __restrict__ kvw, const float* __restrict__ pw) {
    int gi = blockIdx.x * blockDim.x + threadIdx.x;
    if (gi < 4096) {
        int i = gi;
        int lane = i & 31, ks = (i >> 5) & 1, qb = (i >> 6) & 7, h = i >> 9;
        int g = lane >> 2, t = lane & 3;
        int q0 = qb * 16 + g;
        uint4 hi, lo;
        int d0 = h * 32 + (8 * ks + t) * 2;
        int d1 = h * 32 + (8 * ks + t + 4) * 2;
        hi.x = pack2(e[q0 * DIM + d0] * SCALE, e[q0 * DIM + d0 + 1] * SCALE, lo.x);
        hi.y = pack2(e[(q0 + 8) * DIM + d0] * SCALE, e[(q0 + 8) * DIM + d0 + 1] * SCALE, lo.y);
        hi.z = pack2(e[q0 * DIM + d1] * SCALE, e[q0 * DIM + d1 + 1] * SCALE, lo.z);
        hi.w = pack2(e[(q0 + 8) * DIM + d1] * SCALE, e[(q0 + 8) * DIM + d1 + 1] * SCALE, lo.w);
        g_q4h[i] = hi; g_q4l[i] = lo;
    } else if (gi < 4096 + 16384) {
        int i = gi - 4096;
        int lane = i & 31, j = (i >> 5) & 7, qb = (i >> 8) & 7, h = i >> 11;
        int g = lane >> 2, t = lane & 3;
        int r0 = (qb * 16 + g) & 63, r1 = (qb * 16 + g + 8) & 63;
        int c = 8 * j + 2 * t;
        float4 v;
        v.x = bias_val(rpb, h, r0, c);
        v.y = bias_val(rpb, h, r0, c + 1);
        v.z = bias_val(rpb, h, r1, c);
        v.w = bias_val(rpb, h, r1, c + 1);
        g_b4[i] = v;
    } else if (gi < 4096 + 16384 + 32768) {
        int i = gi - 20480;
        int n = i & 511, t = (i >> 9) & 3, kcg = i >> 11;   // 0..15
        int kwA = kcg * 8 + t, kwB = kwA + 4;
        uint4 v;
        v.x = pack2(kvw[n * 256 + 2 * kwA], kvw[n * 256 + 2 * kwA + 1], v.z);
        v.y = pack2(kvw[n * 256 + 2 * kwB], kvw[n * 256 + 2 * kwB + 1], v.w);
        g_kvw4[i] = v;
    } else if (gi < 4096 + 16384 + 32768 + 16384) {
        int ii = gi - 53248;
        int n = ii & 255, t = (ii >> 8) & 3, kc = ii >> 10;  // 0..15
        int kwA = kc * 8 + t, kwB = kwA + 4;
        uint4 v;
        v.x = pack2(pw[n * 256 + 2 * kwA], pw[n * 256 + 2 * kwA + 1], v.z);
        v.y = pack2(pw[n * 256 + 2 * kwB], pw[n * 256 + 2 * kwB + 1], v.w);
        g_pw4[ii] = v;
    }
}

// ---------------- fused window kernel (KV GEMM + attention + proj) -----------
// smem (uint4 units):
//  a4  @ 0      size 4352  (hi [kcg*136 + t*34 + m*8 + g], lo +2176)
//                phase2: V [ks*1024 + d*4 + tq];  phase3: O/A [kc*520+t*130+qb*16+plane*8+g]
//  k4  @ 4352   size 4352  [key*68 + G*4 + t]     (phase3: part of O/A)
//  ws4 @ 8704   size 4112  KV: ping-pong 2x2056 [buf*2056 + t*514 + n]
//                          proj: ping-pong 2x1096 [buf*1096 + t*274 + n]
//  kvb @ uint4 12816 (512 floats)
// total 12944 uint4 = 207104 bytes
#define A4_OFF  0
#define K4_OFF  4352
#define WS4_OFF 8704
#define SMEM_BYTES 207104

extern __shared__ uint4 sm4[];

__global__ __launch_bounds__(512, 1)
void win_attn(const float* __restrict__ x, const float* __restrict__ kvb,
              const float* __restrict__ pb, float* __restrict__ out) {
    const int tid  = threadIdx.x;
    const int bw   = blockIdx.x;
    const int b    = bw >> 10;
    const int wr   = (bw >> 5) & 31;
    const int wc   = bw & 31;
    const int w    = tid >> 5;
    const int lane = tid & 31;
    const int g    = lane >> 2;
    const int t    = lane & 3;
    float* kvbf = (float*)(sm4 + 12816);
    uint32_t* a4w = (uint32_t*)sm4;
    uint32_t smem_base;
    asm("{ .reg .u64 tmp; cvta.to.shared.u64 tmp, %1; cvt.u32.u64 %0, tmp; }"
        : "=r"(smem_base) : "l"((void*)sm4));

    // ---- prologue: stage kvw kcg0 via cp.async ----
    {
        #pragma unroll
        for (int k = 0; k < 4; k++) {
            int gi = tid + k * 512;
            int n = gi & 511, tt = gi >> 9;
            cp16(smem_base + (WS4_OFF + tt * 514 + n) * 16, &g_kvw4[gi]);
        }
        CP_COMMIT();
    }

    // ---- load window tile, split+pack, scatter into a4 fragment layout ----
    {
        const float4* xv = (const float4*)(x +
            ((size_t)((b * 256 + wr * 8) * 256 + wc * 8)) * 256);
        #pragma unroll
        for (int i = 0; i < 8; i++) {
            int idx = tid + i * 512;
            int tok = idx >> 6, c4 = idx & 63;
            int r = tok >> 3, cc = tok & 7;
            float4 v = xv[r * 16384 + cc * 64 + c4];
            int m = tok >> 4, gg = tok & 15;
            int g2 = gg & 7, r8 = gg >> 3;
            int kcg = c4 >> 2, rem = c4 & 3;
            uint32_t lo0, lo1;
            uint32_t hi0 = pack2(v.x, v.y, lo0);
            uint32_t hi1 = pack2(v.z, v.w, lo1);
            int tt0 = 2 * rem, tt1 = tt0 + 1;
            int i0 = kcg * 136 + (tt0 & 3) * 34 + m * 8 + g2;
            int w0 = r8 + 2 * (tt0 >> 2);
            a4w[i0 * 4 + w0] = hi0;
            a4w[(i0 + 2176) * 4 + w0] = lo0;
            int i1 = kcg * 136 + (tt1 & 3) * 34 + m * 8 + g2;
            int w1 = r8 + 2 * (tt1 >> 2);
            a4w[i1 * 4 + w1] = hi1;
            a4w[(i1 + 2176) * 4 + w1] = lo1;
        }
        kvbf[tid] = kvb[tid];
    }

    // ---- KV GEMM: RACE-FREE pipeline (wait -> barrier -> issue -> compute) ----
    const int wmK = (w >> 3) * 32;
    const int wnK = (w & 7) * 64;
    const int mB  = (w >> 3) * 2;

    float acc[2][8][4];
    #pragma unroll
    for (int mt = 0; mt < 2; mt++)
        #pragma unroll
        for (int j = 0; j < 8; j++)
            #pragma unroll
            for (int e = 0; e < 4; e++) acc[mt][j][e] = 0.f;

    for (int kcg = 0; kcg < 16; kcg++) {
        CP_WAIT0();        // group kcg landed
        __syncthreads();   // all warps done reading buf[(kcg+1)&1] (iter kcg-1 compute)
                           // first iter: also makes a4 scatter + kvbf visible
        if (kcg + 1 < 16) {
            int bufn = (kcg + 1) & 1;
            #pragma unroll
            for (int k = 0; k < 4; k++) {
                int gi = tid + k * 512;
                int n = gi & 511, tt = gi >> 9;
                cp16(smem_base + (WS4_OFF + bufn * 2056 + tt * 514 + n) * 16,
                     &g_kvw4[(kcg + 1) * 2048 + gi]);
            }
            CP_COMMIT();
        }
        int bufc = WS4_OFF + (kcg & 1) * 2056;
        uint4 Ah[2], Al[2];
        #pragma unroll
        for (int mt = 0; mt < 2; mt++) {
            int ai = A4_OFF + kcg * 136 + t * 34 + (mB + mt) * 8 + g;
            Ah[mt] = sm4[ai];
            Al[mt] = sm4[ai + 2176];
        }
        #pragma unroll
        for (int j = 0; j < 8; j++) {
            uint4 B = sm4[bufc + t * 514 + wnK + 8 * j + g];
            mma3(acc[0][j], Ah[0], Al[0], B);
            mma3(acc[1][j], Ah[1], Al[1], B);
        }
    }
    __syncthreads();   // all a4 reads done (V will alias a4)

    // ---- epilogues: K warps (wnK<256) -> k4 ; V warps -> a4 alias ----
    if (wnK < 256) {
        #pragma unroll
        for (int mt = 0; mt < 2; mt++) {
            int key0 = wmK + mt * 16 + g;
            #pragma unroll
            for (int jp = 0; jp < 4; jp++) {
                int j = 2 * jp;
                int c  = wnK + 8 * j + 2 * t;
                int c2 = c + 8;
                float b0 = kvbf[c], b1 = kvbf[c + 1];
                float b2 = kvbf[c2], b3 = kvbf[c2 + 1];
                int G = (wnK >> 4) + jp;
                uint4 u;
                u.x = pack2(acc[mt][j][0] + b0, acc[mt][j][1] + b1, u.z);
                u.y = pack2(acc[mt][j + 1][0] + b2, acc[mt][j + 1][1] + b3, u.w);
                sm4[K4_OFF + key0 * 68 + G * 4 + t] = u;
                uint4 v;
                v.x = pack2(acc[mt][j][2] + b0, acc[mt][j][3] + b1, v.z);
                v.y = pack2(acc[mt][j + 1][2] + b2, acc[mt][j + 1][3] + b3, v.w);
                sm4[K4_OFF + (key0 + 8) * 68 + G * 4 + t] = v;
            }
        }
    } else {
        #pragma unroll
        for (int mt = 0; mt < 2; mt++) {
            int ks = mB + mt;
            #pragma unroll
            for (int j = 0; j < 8; j++) {
                int c = wnK - 256 + 8 * j + 2 * t;
                float b0 = kvbf[256 + c], b1 = kvbf[256 + c + 1];
                float v0 = acc[mt][j][0] + b0, v1 = acc[mt][j][1] + b1;
                float v2 = acc[mt][j][2] + b0, v3 = acc[mt][j][3] + b1;
                float o0 = __shfl_xor_sync(0xffffffffu, v0, 4);
                float o1 = __shfl_xor_sync(0xffffffffu, v1, 4);
                float o2 = __shfl_xor_sync(0xffffffffu, v2, 4);
                float o3 = __shfl_xor_sync(0xffffffffu, v3, 4);
                if ((g & 1) == 0) {
                    int tq = g >> 1;
                    uint4 u;
                    u.x = pack2(v0, o0, u.z);
                    u.y = pack2(v2, o2, u.w);
                    sm4[A4_OFF + ks * 1024 + c * 4 + tq] = u;
                    uint4 v;
                    v.x = pack2(v1, o1, v.z);
                    v.y = pack2(v3, o3, v.w);
                    sm4[A4_OFF + ks * 1024 + (c + 1) * 4 + tq] = v;
                }
            }
        }
    }
    __syncthreads();

    // ---- attention: 16 warps = 8 q-blocks x 2 head-groups; O kept in regs ----
    const int qb = w >> 1;
    const int hbase = (w & 1) * 4;
    uint32_t Ohi[4][8], Olo[4][8];

    #pragma unroll
    for (int hh = 0; hh < 4; hh++) {
        const int h = hbase + hh;

        float sacc[8][4];
        #pragma unroll
        for (int j = 0; j < 8; j++) {
            float4 bv = __ldg(&g_b4[((h * 8 + qb) * 8 + j) * 32 + lane]);
            sacc[j][0] = bv.x; sacc[j][1] = bv.y;
            sacc[j][2] = bv.z; sacc[j][3] = bv.w;
        }
        #pragma unroll
        for (int ks = 0; ks < 2; ks++) {
            uint4 Qh = __ldg(&g_q4h[((h * 8 + qb) * 2 + ks) * 32 + lane]);
            uint4 Ql = __ldg(&g_q4l[((h * 8 + qb) * 2 + ks) * 32 + lane]);
            #pragma unroll
            for (int j = 0; j < 8; j++) {
                uint4 K = sm4[K4_OFF + (8 * j + g) * 68 + (h * 2 + ks) * 4 + t];
                mma3(sacc[j], Qh, Ql, K);
            }
        }

        // softmax over 64 keys (rows in 4-lane groups)
        float m0 = -1e30f, m1 = -1e30f;
        #pragma unroll
        for (int j = 0; j < 8; j++) {
            m0 = fmaxf(m0, fmaxf(sacc[j][0], sacc[j][1]));
            m1 = fmaxf(m1, fmaxf(sacc[j][2], sacc[j][3]));
        }
        m0 = fmaxf(m0, __shfl_xor_sync(0xffffffffu, m0, 1));
        m0 = fmaxf(m0, __shfl_xor_sync(0xffffffffu, m0, 2));
        m1 = fmaxf(m1, __shfl_xor_sync(0xffffffffu, m1, 1));
        m1 = fmaxf(m1, __shfl_xor_sync(0xffffffffu, m1, 2));
        float s0 = 0.f, s1 = 0.f;
        #pragma unroll
        for (int j = 0; j < 8; j++) {
            sacc[j][0] = __expf(sacc[j][0] - m0); s0 += sacc[j][0];
            sacc[j][1] = __expf(sacc[j][1] - m0); s0 += sacc[j][1];
            sacc[j][2] = __expf(sacc[j][2] - m1); s1 += sacc[j][2];
            sacc[j][3] = __expf(sacc[j][3] - m1); s1 += sacc[j][3];
        }
        s0 += __shfl_xor_sync(0xffffffffu, s0, 1);
        s0 += __shfl_xor_sync(0xffffffffu, s0, 2);
        s1 += __shfl_xor_sync(0xffffffffu, s1, 1);
        s1 += __shfl_xor_sync(0xffffffffu, s1, 2);
        float inv0 = 1.0f / s0, inv1 = 1.0f / s1;
        #pragma unroll
        for (int j = 0; j < 8; j++) {
            sacc[j][0] *= inv0; sacc[j][1] *= inv0;
            sacc[j][2] *= inv1; sacc[j][3] *= inv1;
        }

        // O = P V (A-fragments repacked from sacc in registers)
        float oacc[4][4];
        #pragma unroll
        for (int j = 0; j < 4; j++)
            #pragma unroll
            for (int e = 0; e < 4; e++) oacc[j][e] = 0.f;

        #pragma unroll
        for (int ks = 0; ks < 4; ks++) {
            uint4 ah, al;
            ah.x = pack2(sacc[2 * ks][0], sacc[2 * ks][1], al.x);
            ah.y = pack2(sacc[2 * ks][2], sacc[2 * ks][3], al.y);
            ah.z = pack2(sacc[2 * ks + 1][0], sacc[2 * ks + 1][1], al.z);
            ah.w = pack2(sacc[2 * ks + 1][2], sacc[2 * ks + 1][3], al.w);
            #pragma unroll
            for (int j = 0; j < 4; j++) {
                uint4 V = sm4[A4_OFF + ks * 1024 + (h * 32 + 8 * j + g) * 4 + t];
                mma3(oacc[j], ah, al, V);
            }
        }

        // pack O into registers (retained across heads)
        #pragma unroll
        for (int jp = 0; jp < 2; jp++) {
            int j = 2 * jp;
            Ohi[hh][jp * 4 + 0] = pack2(oacc[j][0], oacc[j][1], Olo[hh][jp * 4 + 0]);
            Ohi[hh][jp * 4 + 1] = pack2(oacc[j][2], oacc[j][3], Olo[hh][jp * 4 + 1]);
            Ohi[hh][jp * 4 + 2] = pack2(oacc[j + 1][0], oacc[j + 1][1], Olo[hh][jp * 4 + 2]);
            Ohi[hh][jp * 4 + 3] = pack2(oacc[j + 1][2], oacc[j + 1][3], Olo[hh][jp * 4 + 3]);
        }
    }
    __syncthreads();   // all K/V smem reads complete

    // ---- write O fragments into smem A region (a4+k4 reused) ----
    #pragma unroll
    for (int hh = 0; hh < 4; hh++) {
        #pragma unroll
        for (int jp = 0; jp < 2; jp++) {
            int kc = (hbase + hh) * 2 + jp;
            int base = kc * 520 + t * 130 + qb * 16;
            sm4[base + g] = make_uint4(Ohi[hh][jp * 4 + 0], Ohi[hh][jp * 4 + 1],
                                       Ohi[hh][jp * 4 + 2], Ohi[hh][jp * 4 + 3]);
            sm4[base + 8 + g] = make_uint4(Olo[hh][jp * 4 + 0], Olo[hh][jp * 4 + 1],
                                           Olo[hh][jp * 4 + 2], Olo[hh][jp * 4 + 3]);
        }
    }

    // prologue for proj B staging (kc=0) — ws4 has no readers here (barriers above)
    {
        #pragma unroll
        for (int k = 0; k < 2; k++) {
            int gi = tid + k * 512;
            int n = gi & 255, tt = gi >> 8;
            cp16(smem_base + (WS4_OFF + tt * 274 + n) * 16, &g_pw4[gi]);
        }
        CP_COMMIT();
    }

    // ---- proj phase: out = O @ pw^T + pb ; race-free pipeline ----
    const int wmP = (w >> 2) * 32;
    const int wnP = (w & 3) * 64;
    const int qB  = (w >> 2) * 2;

    float pacc[2][8][4];
    #pragma unroll
    for (int mt = 0; mt < 2; mt++)
        #pragma unroll
        for (int j = 0; j < 8; j++)
            #pragma unroll
            for (int e = 0; e < 4; e++) pacc[mt][j][e] = 0.f;

    for (int kc = 0; kc < 16; kc++) {
        CP_WAIT0();        // group kc landed
        __syncthreads();   // all warps done reading buf[(kc+1)&1]; first iter: O frags visible
        if (kc + 1 < 16) {
            int bufn = (kc + 1) & 1;
            #pragma unroll
            for (int k = 0; k < 2; k++) {
                int gi = tid + k * 512;
                int n = gi & 255, tt = gi >> 8;
                cp16(smem_base + (WS4_OFF + bufn * 1096 + tt * 274 + n) * 16,
                     &g_pw4[(kc + 1) * 1024 + gi]);
            }
            CP_COMMIT();
        }
        int bufc = WS4_OFF + (kc & 1) * 1096;
        uint4 Ah[2], Al[2];
        #pragma unroll
        for (int mt = 0; mt < 2; mt++) {
            int ai = kc * 520 + t * 130 + (qB + mt) * 16;
            Ah[mt] = sm4[ai + g];
            Al[mt] = sm4[ai + 8 + g];
        }
        #pragma unroll
        for (int j = 0; j < 8; j++) {
            uint4 B = sm4[bufc + t * 274 + wnP + 8 * j + g];
            mma3(pacc[0][j], Ah[0], Al[0], B);
            mma3(pacc[1][j], Ah[1], Al[1], B);
        }
    }

    // epilogue
    #pragma unroll
    for (int j = 0; j < 8; j++) {
        int oc = wnP + 8 * j + 2 * t;
        float b0 = __ldg(pb + oc), b1 = __ldg(pb + oc + 1);
        #pragma unroll
        for (int mt = 0; mt < 2; mt++) {
            size_t r = (size_t)bw * 128 + wmP + mt * 16 + g;
            *(float2*)(out + r * 256 + oc) =
                make_float2(pacc[mt][j][0] + b0, pacc[mt][j][1] + b1);
            *(float2*)(out + (r + 8) * 256 + oc) =
                make_float2(pacc[mt][j][2] + b0, pacc[mt][j][3] + b1);
        }
    }
}

// ---------------- launch ----------------
static const float* find_by_size(void* const* d_in, const int* in_sizes,
                                 int n_in, int want) {
    for (int i = 0; i < n_in; i++)
        if (in_sizes[i] == want) return (const float*)d_in[i];
    return nullptr;
}

extern "C" void kernel_launch(void* const* d_in, const int* in_sizes, int n_in,
                              void* d_out, int out_size) {
    const float* embeds = find_by_size(d_in, in_sizes, n_in, 128 * 256);
    const float* x      = find_by_size(d_in, in_sizes, n_in, 2 * 256 * 256 * 256);
    const float* rpb    = find_by_size(d_in, in_sizes, n_in, 225 * 8);
    const float* kvw    = find_by_size(d_in, in_sizes, n_in, 512 * 256);
    const float* kvb    = find_by_size(d_in, in_sizes, n_in, 512);
    const float* pw     = find_by_size(d_in, in_sizes, n_in, 256 * 256);
    const float* pb     = find_by_size(d_in, in_sizes, n_in, 256);
    float* out = (float*)d_out;

    prep_all<<<272, 256>>>(embeds, rpb, kvw, pw);

    cudaFuncSetAttribute(win_attn,
                         cudaFuncAttributeMaxDynamicSharedMemorySize, SMEM_BYTES);
    win_attn<<<NWIN, 512, SMEM_BYTES>>>(x, kvb, pb, out);
}

// round 13
// speedup vs baseline: 1.2255x; 1.1251x over previous
#include <cuda_runtime.h>
#include <cuda_bf16.h>
#include <math.h>
#include <stdint.h>

#define DIM 256
#define HEADS 8
#define WIN 64
#define N1 128
#define NWIN 2048
#define SCALE 0.17677669529663687f

// ---------------- device scratch (fragment-packed) ----------------
__device__ uint4 g_q4h[8 * 8 * 2 * 32];          // [h][qb][ks][lane]
__device__ uint4 g_q4l[8 * 8 * 2 * 32];
__device__ float4 g_b4[8 * 8 * 8 * 32];          // [h][qb][j][lane]
__device__ uint4 g_kvw4[16 * 4 * 512];           // [kcg][t][n]
__device__ uint4 g_pw4[16 * 4 * 256];            // [kc][t][n]

// ---------------- helpers ----------------
__device__ __forceinline__ uint32_t pack2(float x0, float x1, uint32_t& lo) {
    __nv_bfloat16 h0 = __float2bfloat16(x0);
    __nv_bfloat16 h1 = __float2bfloat16(x1);
    __nv_bfloat16 l0 = __float2bfloat16(x0 - __bfloat162float(h0));
    __nv_bfloat16 l1 = __float2bfloat16(x1 - __bfloat162float(h1));
    lo = ((uint32_t)__bfloat16_as_ushort(l1) << 16) | (uint32_t)__bfloat16_as_ushort(l0);
    return ((uint32_t)__bfloat16_as_ushort(h1) << 16) | (uint32_t)__bfloat16_as_ushort(h0);
}

__device__ __forceinline__ void mma16(float c[4], uint32_t a0, uint32_t a1,
                                      uint32_t a2, uint32_t a3,
                                      uint32_t b0, uint32_t b1) {
    asm volatile(
        "mma.sync.aligned.m16n8k16.row.col.f32.bf16.bf16.f32 "
        "{%0,%1,%2,%3},{%4,%5,%6,%7},{%8,%9},{%0,%1,%2,%3};\n"
        : "+f"(c[0]), "+f"(c[1]), "+f"(c[2]), "+f"(c[3])
        : "r"(a0), "r"(a1), "r"(a2), "r"(a3), "r"(b0), "r"(b1));
}
__device__ __forceinline__ void mma3(float c[4], const uint4& ah, const uint4& al,
                                     const uint4& B) {
    mma16(c, ah.x, ah.y, ah.z, ah.w, B.x, B.y);
    mma16(c, ah.x, ah.y, ah.z, ah.w, B.z, B.w);
    mma16(c, al.x, al.y, al.z, al.w, B.x, B.y);
}

__device__ __forceinline__ void cp16(uint32_t dst_smem, const void* src) {
    asm volatile("cp.async.cg.shared.global [%0], [%1], 16;\n"
                 :: "r"(dst_smem), "l"(src));
}
#define CP_COMMIT() asm volatile("cp.async.commit_group;\n")
#define CP_WAIT0()  asm volatile("cp.async.wait_group 0;\n")

__device__ __forceinline__ void barn(int id, int cnt) {
    asm volatile("bar.sync %0, %1;" :: "r"(id), "r"(cnt) : "memory");
}

// bias formula (relative position)
__device__ __forceinline__ float bias_val(const float* rpb, int h, int r, int k) {
    int i1 = r >> 3, j1 = r & 7, i2 = k >> 3, j2 = k & 7;
    int idx = (i1 - i2 + 7) * 15 + (j1 - j2 + 7);
    return rpb[idx * HEADS + h];
}

// ---------------- merged prep kernel ----------------
__global__ void prep_all(const float* __restrict__ e, const float* __restrict__ rpb,
                         const float* __restrict__ kvw, const float* __restrict__ pw) {
    int gi = blockIdx.x * blockDim.x + threadIdx.x;
    if (gi < 4096) {
        int i = gi;
        int lane = i & 31, ks = (i >> 5) & 1, qb = (i >> 6) & 7, h = i >> 9;
        int g = lane >> 2, t = lane & 3;
        int q0 = qb * 16 + g;
        uint4 hi, lo;
        int d0 = h * 32 + (8 * ks + t) * 2;
        int d1 = h * 32 + (8 * ks + t + 4) * 2;
        hi.x = pack2(e[q0 * DIM + d0] * SCALE, e[q0 * DIM + d0 + 1] * SCALE, lo.x);
        hi.y = pack2(e[(q0 + 8) * DIM + d0] * SCALE, e[(q0 + 8) * DIM + d0 + 1] * SCALE, lo.y);
        hi.z = pack2(e[q0 * DIM + d1] * SCALE, e[q0 * DIM + d1 + 1] * SCALE, lo.z);
        hi.w = pack2(e[(q0 + 8) * DIM + d1] * SCALE, e[(q0 + 8) * DIM + d1 + 1] * SCALE, lo.w);
        g_q4h[i] = hi; g_q4l[i] = lo;
    } else if (gi < 4096 + 16384) {
        int i = gi - 4096;
        int lane = i & 31, j = (i >> 5) & 7, qb = (i >> 8) & 7, h = i >> 11;
        int g = lane >> 2, t = lane & 3;
        int r0 = (qb * 16 + g) & 63, r1 = (qb * 16 + g + 8) & 63;
        int c = 8 * j + 2 * t;
        float4 v;
        v.x = bias_val(rpb, h, r0, c);
        v.y = bias_val(rpb, h, r0, c + 1);
        v.z = bias_val(rpb, h, r1, c);
        v.w = bias_val(rpb, h, r1, c + 1);
        g_b4[i] = v;
    } else if (gi < 4096 + 16384 + 32768) {
        int i = gi - 20480;
        int n = i & 511, t = (i >> 9) & 3, kcg = i >> 11;   // 0..15
        int kwA = kcg * 8 + t, kwB = kwA + 4;
        uint4 v;
        v.x = pack2(kvw[n * 256 + 2 * kwA], kvw[n * 256 + 2 * kwA + 1], v.z);
        v.y = pack2(kvw[n * 256 + 2 * kwB], kvw[n * 256 + 2 * kwB + 1], v.w);
        g_kvw4[i] = v;
    } else if (gi < 4096 + 16384 + 32768 + 16384) {
        int ii = gi - 53248;
        int n = ii & 255, t = (ii >> 8) & 3, kc = ii >> 10;  // 0..15
        int kwA = kc * 8 + t, kwB = kwA + 4;
        uint4 v;
        v.x = pack2(pw[n * 256 + 2 * kwA], pw[n * 256 + 2 * kwA + 1], v.z);
        v.y = pack2(pw[n * 256 + 2 * kwB], pw[n * 256 + 2 * kwB + 1], v.w);
        g_pw4[ii] = v;
    }
}

// ---------------- fused window kernel (KV GEMM + attention + proj) -----------
// smem (uint4 units):
//  a4  @ 0      size 4352  (hi [kcg*136 + t*34 + m*8 + g], lo +2176)
//                phase2: V [ks*1024 + d*4 + tq];  phase3: O/A [kc*520+t*130+qb*16+plane*8+g]
//  k4  @ 4352   size 4352  [key*68 + G*4 + t]     (phase3: part of O/A)
//  ws4 @ 8704   size 4224  per-group B slices:
//                KV:  pair p (warps {p,p+8}) owns [p*528 + buf*264 + t*66 + n'] n'=0..63
//                proj: grp c (warps w&3==c)  owns [c*528 + buf*264 + t*66 + n']
//  kvb @ uint4 12928 (512 floats)
// total 13056 uint4 = 208896 bytes
#define A4_OFF  0
#define K4_OFF  4352
#define WS4_OFF 8704
#define SMEM_BYTES 208896

extern __shared__ uint4 sm4[];

__global__ __launch_bounds__(512, 1)
void win_attn(const float* __restrict__ x, const float* __restrict__ kvb,
              const float* __restrict__ pb, float* __restrict__ out) {
    const int tid  = threadIdx.x;
    const int bw   = blockIdx.x;
    const int b    = bw >> 10;
    const int wr   = (bw >> 5) & 31;
    const int wc   = bw & 31;
    const int w    = tid >> 5;
    const int lane = tid & 31;
    const int g    = lane >> 2;
    const int t    = lane & 3;
    float* kvbf = (float*)(sm4 + 12928);
    uint32_t* a4w = (uint32_t*)sm4;
    uint32_t smem_base;
    asm("{ .reg .u64 tmp; cvta.to.shared.u64 tmp, %1; cvt.u32.u64 %0, tmp; }"
        : "=r"(smem_base) : "l"((void*)sm4));

    // slice-group ids
    const int p    = w & 7;              // KV pair id (warps {p, p+8})
    const int sub  = w >> 3;             // which half of the slice this warp stages
    const int q32  = lane + sub * 32;    // n' 0..63 staged by this thread
    const int SKV0 = WS4_OFF + p * 528;

    // ---- KV prologue: each pair stages its kcg0 slice ----
    #pragma unroll
    for (int k = 0; k < 4; k++)
        cp16(smem_base + (SKV0 + k * 66 + q32) * 16,
             &g_kvw4[k * 512 + p * 64 + q32]);
    CP_COMMIT();

    // ---- load window tile, split+pack, scatter into a4 fragment layout ----
    {
        const float4* xv = (const float4*)(x +
            ((size_t)((b * 256 + wr * 8) * 256 + wc * 8)) * 256);
        #pragma unroll
        for (int i = 0; i < 8; i++) {
            int idx = tid + i * 512;
            int tok = idx >> 6, c4 = idx & 63;
            int r = tok >> 3, cc = tok & 7;
            float4 v = xv[r * 16384 + cc * 64 + c4];
            int m = tok >> 4, gg = tok & 15;
            int g2 = gg & 7, r8 = gg >> 3;
            int kcg = c4 >> 2, rem = c4 & 3;
            uint32_t lo0, lo1;
            uint32_t hi0 = pack2(v.x, v.y, lo0);
            uint32_t hi1 = pack2(v.z, v.w, lo1);
            int tt0 = 2 * rem, tt1 = tt0 + 1;
            int i0 = kcg * 136 + (tt0 & 3) * 34 + m * 8 + g2;
            int w0 = r8 + 2 * (tt0 >> 2);
            a4w[i0 * 4 + w0] = hi0;
            a4w[(i0 + 2176) * 4 + w0] = lo0;
            int i1 = kcg * 136 + (tt1 & 3) * 34 + m * 8 + g2;
            int w1 = r8 + 2 * (tt1 >> 2);
            a4w[i1 * 4 + w1] = hi1;
            a4w[(i1 + 2176) * 4 + w1] = lo1;
        }
        kvbf[tid] = kvb[tid];
    }
    __syncthreads();   // a4 (A fragments) + kvbf stable and visible from here

    // ---- KV GEMM: per-pair pipelined slices; NO CTA barriers in loop ----
    const int wmK = (w >> 3) * 32;
    const int wnK = p * 64;
    const int mB  = (w >> 3) * 2;

    float acc[2][8][4];
    #pragma unroll
    for (int mt = 0; mt < 2; mt++)
        #pragma unroll
        for (int j = 0; j < 8; j++)
            #pragma unroll
            for (int e = 0; e < 4; e++) acc[mt][j][e] = 0.f;

    for (int kcg = 0; kcg < 16; kcg++) {
        // A fragments: a4 immutable during loop -> safe to load any time
        uint4 Ah[2], Al[2];
        #pragma unroll
        for (int mt = 0; mt < 2; mt++) {
            int ai = A4_OFF + kcg * 136 + t * 34 + (mB + mt) * 8 + g;
            Ah[mt] = sm4[ai];
            Al[mt] = sm4[ai + 2176];
        }
        CP_WAIT0();            // this thread's slice half landed
        barn(1 + p, 64);       // partner done staging AND done reading old buffer
        if (kcg + 1 < 16) {
            int Sn = SKV0 + ((kcg + 1) & 1) * 264;
            #pragma unroll
            for (int k = 0; k < 4; k++)
                cp16(smem_base + (Sn + k * 66 + q32) * 16,
                     &g_kvw4[(kcg + 1) * 2048 + k * 512 + p * 64 + q32]);
            CP_COMMIT();
        }
        int Sc = SKV0 + (kcg & 1) * 264;
        #pragma unroll
        for (int j = 0; j < 8; j++) {
            uint4 B = sm4[Sc + t * 66 + 8 * j + g];
            mma3(acc[0][j], Ah[0], Al[0], B);
            mma3(acc[1][j], Ah[1], Al[1], B);
        }
    }
    __syncthreads();   // all a4 + ws4 reads done (V will alias a4; proj reuses ws4)

    // ---- proj kc=0 slice prologue: issue NOW, lands during attention ----
    const int cg   = w & 3;               // proj slice group (4 warps)
    const int l128 = (w >> 2) * 32 + lane;
    const int SP0  = WS4_OFF + cg * 528;
    #pragma unroll
    for (int k = 0; k < 2; k++) {
        int elem = k * 128 + l128;
        int tt = elem >> 6, q = elem & 63;
        cp16(smem_base + (SP0 + tt * 66 + q) * 16,
             &g_pw4[tt * 256 + cg * 64 + q]);
    }
    CP_COMMIT();

    // ---- epilogues: K warps (wnK<256) -> k4 ; V warps -> a4 alias ----
    if (wnK < 256) {
        #pragma unroll
        for (int mt = 0; mt < 2; mt++) {
            int key0 = wmK + mt * 16 + g;
            #pragma unroll
            for (int jp = 0; jp < 4; jp++) {
                int j = 2 * jp;
                int c  = wnK + 8 * j + 2 * t;
                int c2 = c + 8;
                float b0 = kvbf[c], b1 = kvbf[c + 1];
                float b2 = kvbf[c2], b3 = kvbf[c2 + 1];
                int G = (wnK >> 4) + jp;
                uint4 u;
                u.x = pack2(acc[mt][j][0] + b0, acc[mt][j][1] + b1, u.z);
                u.y = pack2(acc[mt][j + 1][0] + b2, acc[mt][j + 1][1] + b3, u.w);
                sm4[K4_OFF + key0 * 68 + G * 4 + t] = u;
                uint4 v;
                v.x = pack2(acc[mt][j][2] + b0, acc[mt][j][3] + b1, v.z);
                v.y = pack2(acc[mt][j + 1][2] + b2, acc[mt][j + 1][3] + b3, v.w);
                sm4[K4_OFF + (key0 + 8) * 68 + G * 4 + t] = v;
            }
        }
    } else {
        #pragma unroll
        for (int mt = 0; mt < 2; mt++) {
            int ks = mB + mt;
            #pragma unroll
            for (int j = 0; j < 8; j++) {
                int c = wnK - 256 + 8 * j + 2 * t;
                float b0 = kvbf[256 + c], b1 = kvbf[256 + c + 1];
                float v0 = acc[mt][j][0] + b0, v1 = acc[mt][j][1] + b1;
                float v2 = acc[mt][j][2] + b0, v3 = acc[mt][j][3] + b1;
                float o0 = __shfl_xor_sync(0xffffffffu, v0, 4);
                float o1 = __shfl_xor_sync(0xffffffffu, v1, 4);
                float o2 = __shfl_xor_sync(0xffffffffu, v2, 4);
                float o3 = __shfl_xor_sync(0xffffffffu, v3, 4);
                if ((g & 1) == 0) {
                    int tq = g >> 1;
                    uint4 u;
                    u.x = pack2(v0, o0, u.z);
                    u.y = pack2(v2, o2, u.w);
                    sm4[A4_OFF + ks * 1024 + c * 4 + tq] = u;
                    uint4 v;
                    v.x = pack2(v1, o1, v.z);
                    v.y = pack2(v3, o3, v.w);
                    sm4[A4_OFF + ks * 1024 + (c + 1) * 4 + tq] = v;
                }
            }
        }
    }
    __syncthreads();

    // ---- attention: 16 warps = 8 q-blocks x 2 head-groups; O kept in regs ----
    const int qb = w >> 1;
    const int hbase = (w & 1) * 4;
    uint32_t Ohi[4][8], Olo[4][8];

    #pragma unroll
    for (int hh = 0; hh < 4; hh++) {
        const int h = hbase + hh;

        float sacc[8][4];
        #pragma unroll
        for (int j = 0; j < 8; j++) {
            float4 bv = __ldg(&g_b4[((h * 8 + qb) * 8 + j) * 32 + lane]);
            sacc[j][0] = bv.x; sacc[j][1] = bv.y;
            sacc[j][2] = bv.z; sacc[j][3] = bv.w;
        }
        #pragma unroll
        for (int ks = 0; ks < 2; ks++) {
            uint4 Qh = __ldg(&g_q4h[((h * 8 + qb) * 2 + ks) * 32 + lane]);
            uint4 Ql = __ldg(&g_q4l[((h * 8 + qb) * 2 + ks) * 32 + lane]);
            #pragma unroll
            for (int j = 0; j < 8; j++) {
                uint4 K = sm4[K4_OFF + (8 * j + g) * 68 + (h * 2 + ks) * 4 + t];
                mma3(sacc[j], Qh, Ql, K);
            }
        }

        // softmax over 64 keys (rows in 4-lane groups)
        float m0 = -1e30f, m1 = -1e30f;
        #pragma unroll
        for (int j = 0; j < 8; j++) {
            m0 = fmaxf(m0, fmaxf(sacc[j][0], sacc[j][1]));
            m1 = fmaxf(m1, fmaxf(sacc[j][2], sacc[j][3]));
        }
        m0 = fmaxf(m0, __shfl_xor_sync(0xffffffffu, m0, 1));
        m0 = fmaxf(m0, __shfl_xor_sync(0xffffffffu, m0, 2));
        m1 = fmaxf(m1, __shfl_xor_sync(0xffffffffu, m1, 1));
        m1 = fmaxf(m1, __shfl_xor_sync(0xffffffffu, m1, 2));
        float s0 = 0.f, s1 = 0.f;
        #pragma unroll
        for (int j = 0; j < 8; j++) {
            sacc[j][0] = __expf(sacc[j][0] - m0); s0 += sacc[j][0];
            sacc[j][1] = __expf(sacc[j][1] - m0); s0 += sacc[j][1];
            sacc[j][2] = __expf(sacc[j][2] - m1); s1 += sacc[j][2];
            sacc[j][3] = __expf(sacc[j][3] - m1); s1 += sacc[j][3];
        }
        s0 += __shfl_xor_sync(0xffffffffu, s0, 1);
        s0 += __shfl_xor_sync(0xffffffffu, s0, 2);
        s1 += __shfl_xor_sync(0xffffffffu, s1, 1);
        s1 += __shfl_xor_sync(0xffffffffu, s1, 2);
        float inv0 = 1.0f / s0, inv1 = 1.0f / s1;
        #pragma unroll
        for (int j = 0; j < 8; j++) {
            sacc[j][0] *= inv0; sacc[j][1] *= inv0;
            sacc[j][2] *= inv1; sacc[j][3] *= inv1;
        }

        // O = P V (A-fragments repacked from sacc in registers)
        float oacc[4][4];
        #pragma unroll
        for (int j = 0; j < 4; j++)
            #pragma unroll
            for (int e = 0; e < 4; e++) oacc[j][e] = 0.f;

        #pragma unroll
        for (int ks = 0; ks < 4; ks++) {
            uint4 ah, al;
            ah.x = pack2(sacc[2 * ks][0], sacc[2 * ks][1], al.x);
            ah.y = pack2(sacc[2 * ks][2], sacc[2 * ks][3], al.y);
            ah.z = pack2(sacc[2 * ks + 1][0], sacc[2 * ks + 1][1], al.z);
            ah.w = pack2(sacc[2 * ks + 1][2], sacc[2 * ks + 1][3], al.w);
            #pragma unroll
            for (int j = 0; j < 4; j++) {
                uint4 V = sm4[A4_OFF + ks * 1024 + (h * 32 + 8 * j + g) * 4 + t];
                mma3(oacc[j], ah, al, V);
            }
        }

        // pack O into registers (retained across heads)
        #pragma unroll
        for (int jp = 0; jp < 2; jp++) {
            int j = 2 * jp;
            Ohi[hh][jp * 4 + 0] = pack2(oacc[j][0], oacc[j][1], Olo[hh][jp * 4 + 0]);
            Ohi[hh][jp * 4 + 1] = pack2(oacc[j][2], oacc[j][3], Olo[hh][jp * 4 + 1]);
            Ohi[hh][jp * 4 + 2] = pack2(oacc[j + 1][0], oacc[j + 1][1], Olo[hh][jp * 4 + 2]);
            Ohi[hh][jp * 4 + 3] = pack2(oacc[j + 1][2], oacc[j + 1][3], Olo[hh][jp * 4 + 3]);
        }
    }
    __syncthreads();   // all K/V smem reads complete

    // ---- write O fragments into smem A region (a4+k4 reused) ----
    #pragma unroll
    for (int hh = 0; hh < 4; hh++) {
        #pragma unroll
        for (int jp = 0; jp < 2; jp++) {
            int kc = (hbase + hh) * 2 + jp;
            int base = kc * 520 + t * 130 + qb * 16;
            sm4[base + g] = make_uint4(Ohi[hh][jp * 4 + 0], Ohi[hh][jp * 4 + 1],
                                       Ohi[hh][jp * 4 + 2], Ohi[hh][jp * 4 + 3]);
            sm4[base + 8 + g] = make_uint4(Olo[hh][jp * 4 + 0], Olo[hh][jp * 4 + 1],
                                           Olo[hh][jp * 4 + 2], Olo[hh][jp * 4 + 3]);
        }
    }
    __syncthreads();   // O fragments visible (O/A region immutable from here)

    // ---- proj phase: out = O @ pw^T + pb ; per-group pipelined slices ----
    const int wmP = (w >> 2) * 32;
    const int wnP = cg * 64;
    const int qB  = (w >> 2) * 2;

    float pacc[2][8][4];
    #pragma unroll
    for (int mt = 0; mt < 2; mt++)
        #pragma unroll
        for (int j = 0; j < 8; j++)
            #pragma unroll
            for (int e = 0; e < 4; e++) pacc[mt][j][e] = 0.f;

    for (int kc = 0; kc < 16; kc++) {
        // A fragments: O region immutable during loop
        uint4 Ah[2], Al[2];
        #pragma unroll
        for (int mt = 0; mt < 2; mt++) {
            int ai = kc * 520 + t * 130 + (qB + mt) * 16;
            Ah[mt] = sm4[ai + g];
            Al[mt] = sm4[ai + 8 + g];
        }
        CP_WAIT0();            // own slice part landed
        barn(1 + cg, 128);     // group done staging AND done reading old buffer
        if (kc + 1 < 16) {
            int Sn = SP0 + ((kc + 1) & 1) * 264;
            #pragma unroll
            for (int k = 0; k < 2; k++) {
                int elem = k * 128 + l128;
                int tt = elem >> 6, q = elem & 63;
                cp16(smem_base + (Sn + tt * 66 + q) * 16,
                     &g_pw4[(kc + 1) * 1024 + tt * 256 + cg * 64 + q]);
            }
            CP_COMMIT();
        }
        int Sc = SP0 + (kc & 1) * 264;
        #pragma unroll
        for (int j = 0; j < 8; j++) {
            uint4 B = sm4[Sc + t * 66 + 8 * j + g];
            mma3(pacc[0][j], Ah[0], Al[0], B);
            mma3(pacc[1][j], Ah[1], Al[1], B);
        }
    }

    // epilogue
    #pragma unroll
    for (int j = 0; j < 8; j++) {
        int oc = wnP + 8 * j + 2 * t;
        float b0 = __ldg(pb + oc), b1 = __ldg(pb + oc + 1);
        #pragma unroll
        for (int mt = 0; mt < 2; mt++) {
            size_t r = (size_t)bw * 128 + wmP + mt * 16 + g;
            *(float2*)(out + r * 256 + oc) =
                make_float2(pacc[mt][j][0] + b0, pacc[mt][j][1] + b1);
            *(float2*)(out + (r + 8) * 256 + oc) =
                make_float2(pacc[mt][j][2] + b0, pacc[mt][j][3] + b1);
        }
    }
}

// ---------------- launch ----------------
static const float* find_by_size(void* const* d_in, const int* in_sizes,
                                 int n_in, int want) {
    for (int i = 0; i < n_in; i++)
        if (in_sizes[i] == want) return (const float*)d_in[i];
    return nullptr;
}

extern "C" void kernel_launch(void* const* d_in, const int* in_sizes, int n_in,
                              void* d_out, int out_size) {
    const float* embeds = find_by_size(d_in, in_sizes, n_in, 128 * 256);
    const float* x      = find_by_size(d_in, in_sizes, n_in, 2 * 256 * 256 * 256);
    const float* rpb    = find_by_size(d_in, in_sizes, n_in, 225 * 8);
    const float* kvw    = find_by_size(d_in, in_sizes, n_in, 512 * 256);
    const float* kvb    = find_by_size(d_in, in_sizes, n_in, 512);
    const float* pw     = find_by_size(d_in, in_sizes, n_in, 256 * 256);
    const float* pb     = find_by_size(d_in, in_sizes, n_in, 256);
    float* out = (float*)d_out;

    prep_all<<<272, 256>>>(embeds, rpb, kvw, pw);

    cudaFuncSetAttribute(win_attn,
                         cudaFuncAttributeMaxDynamicSharedMemorySize, SMEM_BYTES);
    win_attn<<<NWIN, 512, SMEM_BYTES>>>(x, kvb, pb, out);
}

// round 14
// speedup vs baseline: 1.2315x; 1.0049x over previous
#include <cuda_runtime.h>
#include <cuda_bf16.h>
#include <math.h>
#include <stdint.h>

#define DIM 256
#define HEADS 8
#define WIN 64
#define N1 128
#define NWIN 2048
#define SCALE 0.17677669529663687f
#define LOG2E 1.4426950408889634f

// ---------------- device scratch (fragment-packed) ----------------
__device__ uint4 g_q4h[8 * 8 * 2 * 32];          // [h][qb][ks][lane]  (pre-scaled by SCALE*LOG2E)
__device__ uint4 g_q4l[8 * 8 * 2 * 32];
__device__ float4 g_b4[8 * 8 * 8 * 32];          // [h][qb][j][lane]   (pre-scaled by LOG2E)
__device__ uint4 g_kvw4[16 * 4 * 512];           // [kcg][t][n]
__device__ uint4 g_pw4[16 * 4 * 256];            // [kc][t][n]

// ---------------- helpers ----------------
__device__ __forceinline__ uint32_t pack2(float x0, float x1, uint32_t& lo) {
    __nv_bfloat16 h0 = __float2bfloat16(x0);
    __nv_bfloat16 h1 = __float2bfloat16(x1);
    __nv_bfloat16 l0 = __float2bfloat16(x0 - __bfloat162float(h0));
    __nv_bfloat16 l1 = __float2bfloat16(x1 - __bfloat162float(h1));
    lo = ((uint32_t)__bfloat16_as_ushort(l1) << 16) | (uint32_t)__bfloat16_as_ushort(l0);
    return ((uint32_t)__bfloat16_as_ushort(h1) << 16) | (uint32_t)__bfloat16_as_ushort(h0);
}

// NOTE: non-volatile — pure register op; lets ptxas software-pipeline LDS->HMMA
__device__ __forceinline__ void mma16(float c[4], uint32_t a0, uint32_t a1,
                                      uint32_t a2, uint32_t a3,
                                      uint32_t b0, uint32_t b1) {
    asm("mma.sync.aligned.m16n8k16.row.col.f32.bf16.bf16.f32 "
        "{%0,%1,%2,%3},{%4,%5,%6,%7},{%8,%9},{%0,%1,%2,%3};\n"
        : "+f"(c[0]), "+f"(c[1]), "+f"(c[2]), "+f"(c[3])
        : "r"(a0), "r"(a1), "r"(a2), "r"(a3), "r"(b0), "r"(b1));
}
__device__ __forceinline__ void mma3(float c[4], const uint4& ah, const uint4& al,
                                     const uint4& B) {
    mma16(c, ah.x, ah.y, ah.z, ah.w, B.x, B.y);
    mma16(c, ah.x, ah.y, ah.z, ah.w, B.z, B.w);
    mma16(c, al.x, al.y, al.z, al.w, B.x, B.y);
}

__device__ __forceinline__ float ex2(float x) {
    float r;
    asm("ex2.approx.f32 %0, %1;" : "=f"(r) : "f"(x));
    return r;
}

__device__ __forceinline__ void cp16(uint32_t dst_smem, const void* src) {
    asm volatile("cp.async.cg.shared.global [%0], [%1], 16;\n"
                 :: "r"(dst_smem), "l"(src));
}
#define CP_COMMIT() asm volatile("cp.async.commit_group;\n")
#define CP_WAIT0()  asm volatile("cp.async.wait_group 0;\n")

__device__ __forceinline__ void barn(int id, int cnt) {
    asm volatile("bar.sync %0, %1;" :: "r"(id), "r"(cnt) : "memory");
}

// bias formula (relative position)
__device__ __forceinline__ float bias_val(const float* rpb, int h, int r, int k) {
    int i1 = r >> 3, j1 = r & 7, i2 = k >> 3, j2 = k & 7;
    int idx = (i1 - i2 + 7) * 15 + (j1 - j2 + 7);
    return rpb[idx * HEADS + h];
}

// ---------------- merged prep kernel ----------------
__global__ void prep_all(const float* __restrict__ e, const float* __restrict__ rpb,
                         const float* __restrict__ kvw, const float* __restrict__ pw) {
    int gi = blockIdx.x * blockDim.x + threadIdx.x;
    if (gi < 4096) {
        int i = gi;
        int lane = i & 31, ks = (i >> 5) & 1, qb = (i >> 6) & 7, h = i >> 9;
        int g = lane >> 2, t = lane & 3;
        int q0 = qb * 16 + g;
        const float QS = SCALE * LOG2E;
        uint4 hi, lo;
        int d0 = h * 32 + (8 * ks + t) * 2;
        int d1 = h * 32 + (8 * ks + t + 4) * 2;
        hi.x = pack2(e[q0 * DIM + d0] * QS, e[q0 * DIM + d0 + 1] * QS, lo.x);
        hi.y = pack2(e[(q0 + 8) * DIM + d0] * QS, e[(q0 + 8) * DIM + d0 + 1] * QS, lo.y);
        hi.z = pack2(e[q0 * DIM + d1] * QS, e[q0 * DIM + d1 + 1] * QS, lo.z);
        hi.w = pack2(e[(q0 + 8) * DIM + d1] * QS, e[(q0 + 8) * DIM + d1 + 1] * QS, lo.w);
        g_q4h[i] = hi; g_q4l[i] = lo;
    } else if (gi < 4096 + 16384) {
        int i = gi - 4096;
        int lane = i & 31, j = (i >> 5) & 7, qb = (i >> 8) & 7, h = i >> 11;
        int g = lane >> 2, t = lane & 3;
        int r0 = (qb * 16 + g) & 63, r1 = (qb * 16 + g + 8) & 63;
        int c = 8 * j + 2 * t;
        float4 v;
        v.x = bias_val(rpb, h, r0, c) * LOG2E;
        v.y = bias_val(rpb, h, r0, c + 1) * LOG2E;
        v.z = bias_val(rpb, h, r1, c) * LOG2E;
        v.w = bias_val(rpb, h, r1, c + 1) * LOG2E;
        g_b4[i] = v;
    } else if (gi < 4096 + 16384 + 32768) {
        int i = gi - 20480;
        int n = i & 511, t = (i >> 9) & 3, kcg = i >> 11;   // 0..15
        int kwA = kcg * 8 + t, kwB = kwA + 4;
        uint4 v;
        v.x = pack2(kvw[n * 256 + 2 * kwA], kvw[n * 256 + 2 * kwA + 1], v.z);
        v.y = pack2(kvw[n * 256 + 2 * kwB], kvw[n * 256 + 2 * kwB + 1], v.w);
        g_kvw4[i] = v;
    } else if (gi < 4096 + 16384 + 32768 + 16384) {
        int ii = gi - 53248;
        int n = ii & 255, t = (ii >> 8) & 3, kc = ii >> 10;  // 0..15
        int kwA = kc * 8 + t, kwB = kwA + 4;
        uint4 v;
        v.x = pack2(pw[n * 256 + 2 * kwA], pw[n * 256 + 2 * kwA + 1], v.z);
        v.y = pack2(pw[n * 256 + 2 * kwB], pw[n * 256 + 2 * kwB + 1], v.w);
        g_pw4[ii] = v;
    }
}

// ---------------- fused window kernel (KV GEMM + attention + proj) -----------
// smem layout identical to R13 (see offsets)
#define A4_OFF  0
#define K4_OFF  4352
#define WS4_OFF 8704
#define SMEM_BYTES 208896

extern __shared__ uint4 sm4[];

__global__ __launch_bounds__(512, 1)
void win_attn(const float* __restrict__ x, const float* __restrict__ kvb,
              const float* __restrict__ pb, float* __restrict__ out) {
    const int tid  = threadIdx.x;
    const int bw   = blockIdx.x;
    const int b    = bw >> 10;
    const int wr   = (bw >> 5) & 31;
    const int wc   = bw & 31;
    const int w    = tid >> 5;
    const int lane = tid & 31;
    const int g    = lane >> 2;
    const int t    = lane & 3;
    float* kvbf = (float*)(sm4 + 12928);
    uint32_t* a4w = (uint32_t*)sm4;
    uint32_t smem_base;
    asm("{ .reg .u64 tmp; cvta.to.shared.u64 tmp, %1; cvt.u32.u64 %0, tmp; }"
        : "=r"(smem_base) : "l"((void*)sm4));

    // slice-group ids
    const int p    = w & 7;              // KV pair id (warps {p, p+8})
    const int sub  = w >> 3;
    const int q32  = lane + sub * 32;
    const int SKV0 = WS4_OFF + p * 528;

    // ---- KV prologue: each pair stages its kcg0 slice ----
    #pragma unroll
    for (int k = 0; k < 4; k++)
        cp16(smem_base + (SKV0 + k * 66 + q32) * 16,
             &g_kvw4[k * 512 + p * 64 + q32]);
    CP_COMMIT();

    // ---- load window tile, split+pack, scatter into a4 fragment layout ----
    {
        const float4* xv = (const float4*)(x +
            ((size_t)((b * 256 + wr * 8) * 256 + wc * 8)) * 256);
        #pragma unroll
        for (int i = 0; i < 8; i++) {
            int idx = tid + i * 512;
            int tok = idx >> 6, c4 = idx & 63;
            int r = tok >> 3, cc = tok & 7;
            float4 v = xv[r * 16384 + cc * 64 + c4];
            int m = tok >> 4, gg = tok & 15;
            int g2 = gg & 7, r8 = gg >> 3;
            int kcg = c4 >> 2, rem = c4 & 3;
            uint32_t lo0, lo1;
            uint32_t hi0 = pack2(v.x, v.y, lo0);
            uint32_t hi1 = pack2(v.z, v.w, lo1);
            int tt0 = 2 * rem, tt1 = tt0 + 1;
            int i0 = kcg * 136 + (tt0 & 3) * 34 + m * 8 + g2;
            int w0 = r8 + 2 * (tt0 >> 2);
            a4w[i0 * 4 + w0] = hi0;
            a4w[(i0 + 2176) * 4 + w0] = lo0;
            int i1 = kcg * 136 + (tt1 & 3) * 34 + m * 8 + g2;
            int w1 = r8 + 2 * (tt1 >> 2);
            a4w[i1 * 4 + w1] = hi1;
            a4w[(i1 + 2176) * 4 + w1] = lo1;
        }
        kvbf[tid] = kvb[tid];
    }
    __syncthreads();   // a4 (A fragments) + kvbf stable and visible from here

    // ---- KV GEMM: per-pair pipelined slices; NO CTA barriers in loop ----
    const int wmK = (w >> 3) * 32;
    const int wnK = p * 64;
    const int mB  = (w >> 3) * 2;

    float acc[2][8][4];
    #pragma unroll
    for (int mt = 0; mt < 2; mt++)
        #pragma unroll
        for (int j = 0; j < 8; j++)
            #pragma unroll
            for (int e = 0; e < 4; e++) acc[mt][j][e] = 0.f;

    for (int kcg = 0; kcg < 16; kcg++) {
        uint4 Ah[2], Al[2];
        #pragma unroll
        for (int mt = 0; mt < 2; mt++) {
            int ai = A4_OFF + kcg * 136 + t * 34 + (mB + mt) * 8 + g;
            Ah[mt] = sm4[ai];
            Al[mt] = sm4[ai + 2176];
        }
        CP_WAIT0();
        barn(1 + p, 64);
        if (kcg + 1 < 16) {
            int Sn = SKV0 + ((kcg + 1) & 1) * 264;
            #pragma unroll
            for (int k = 0; k < 4; k++)
                cp16(smem_base + (Sn + k * 66 + q32) * 16,
                     &g_kvw4[(kcg + 1) * 2048 + k * 512 + p * 64 + q32]);
            CP_COMMIT();
        }
        int Sc = SKV0 + (kcg & 1) * 264;
        #pragma unroll
        for (int j = 0; j < 8; j++) {
            uint4 B = sm4[Sc + t * 66 + 8 * j + g];
            mma3(acc[0][j], Ah[0], Al[0], B);
            mma3(acc[1][j], Ah[1], Al[1], B);
        }
    }
    __syncthreads();   // all a4 + ws4 reads done (V will alias a4; proj reuses ws4)

    // ---- proj kc=0 slice prologue: issue NOW, lands during attention ----
    const int cg   = w & 3;
    const int l128 = (w >> 2) * 32 + lane;
    const int SP0  = WS4_OFF + cg * 528;
    #pragma unroll
    for (int k = 0; k < 2; k++) {
        int elem = k * 128 + l128;
        int tt = elem >> 6, q = elem & 63;
        cp16(smem_base + (SP0 + tt * 66 + q) * 16,
             &g_pw4[tt * 256 + cg * 64 + q]);
    }
    CP_COMMIT();

    // ---- epilogues: K warps (wnK<256) -> k4 ; V warps -> a4 alias ----
    if (wnK < 256) {
        #pragma unroll
        for (int mt = 0; mt < 2; mt++) {
            int key0 = wmK + mt * 16 + g;
            #pragma unroll
            for (int jp = 0; jp < 4; jp++) {
                int j = 2 * jp;
                int c  = wnK + 8 * j + 2 * t;
                int c2 = c + 8;
                float b0 = kvbf[c], b1 = kvbf[c + 1];
                float b2 = kvbf[c2], b3 = kvbf[c2 + 1];
                int G = (wnK >> 4) + jp;
                uint4 u;
                u.x = pack2(acc[mt][j][0] + b0, acc[mt][j][1] + b1, u.z);
                u.y = pack2(acc[mt][j + 1][0] + b2, acc[mt][j + 1][1] + b3, u.w);
                sm4[K4_OFF + key0 * 68 + G * 4 + t] = u;
                uint4 v;
                v.x = pack2(acc[mt][j][2] + b0, acc[mt][j][3] + b1, v.z);
                v.y = pack2(acc[mt][j + 1][2] + b2, acc[mt][j + 1][3] + b3, v.w);
                sm4[K4_OFF + (key0 + 8) * 68 + G * 4 + t] = v;
            }
        }
    } else {
        #pragma unroll
        for (int mt = 0; mt < 2; mt++) {
            int ks = mB + mt;
            #pragma unroll
            for (int j = 0; j < 8; j++) {
                int c = wnK - 256 + 8 * j + 2 * t;
                float b0 = kvbf[256 + c], b1 = kvbf[256 + c + 1];
                float v0 = acc[mt][j][0] + b0, v1 = acc[mt][j][1] + b1;
                float v2 = acc[mt][j][2] + b0, v3 = acc[mt][j][3] + b1;
                float o0 = __shfl_xor_sync(0xffffffffu, v0, 4);
                float o1 = __shfl_xor_sync(0xffffffffu, v1, 4);
                float o2 = __shfl_xor_sync(0xffffffffu, v2, 4);
                float o3 = __shfl_xor_sync(0xffffffffu, v3, 4);
                if ((g & 1) == 0) {
                    int tq = g >> 1;
                    uint4 u;
                    u.x = pack2(v0, o0, u.z);
                    u.y = pack2(v2, o2, u.w);
                    sm4[A4_OFF + ks * 1024 + c * 4 + tq] = u;
                    uint4 v;
                    v.x = pack2(v1, o1, v.z);
                    v.y = pack2(v3, o3, v.w);
                    sm4[A4_OFF + ks * 1024 + (c + 1) * 4 + tq] = v;
                }
            }
        }
    }
    __syncthreads();

    // ---- attention: 16 warps = 8 q-blocks x 2 head-groups; O kept in regs ----
    const int qb = w >> 1;
    const int hbase = (w & 1) * 4;
    uint32_t Ohi[4][8], Olo[4][8];

    #pragma unroll
    for (int hh = 0; hh < 4; hh++) {
        const int h = hbase + hh;

        float sacc[8][4];
        #pragma unroll
        for (int j = 0; j < 8; j++) {
            float4 bv = __ldg(&g_b4[((h * 8 + qb) * 8 + j) * 32 + lane]);
            sacc[j][0] = bv.x; sacc[j][1] = bv.y;
            sacc[j][2] = bv.z; sacc[j][3] = bv.w;
        }
        #pragma unroll
        for (int ks = 0; ks < 2; ks++) {
            uint4 Qh = __ldg(&g_q4h[((h * 8 + qb) * 2 + ks) * 32 + lane]);
            uint4 Ql = __ldg(&g_q4l[((h * 8 + qb) * 2 + ks) * 32 + lane]);
            #pragma unroll
            for (int j = 0; j < 8; j++) {
                uint4 K = sm4[K4_OFF + (8 * j + g) * 68 + (h * 2 + ks) * 4 + t];
                mma3(sacc[j], Qh, Ql, K);
            }
        }

        // softmax (base-2 domain; Q/bias pre-scaled by log2e); E unnormalized
        float m0 = -1e30f, m1 = -1e30f;
        #pragma unroll
        for (int j = 0; j < 8; j++) {
            m0 = fmaxf(m0, fmaxf(sacc[j][0], sacc[j][1]));
            m1 = fmaxf(m1, fmaxf(sacc[j][2], sacc[j][3]));
        }
        m0 = fmaxf(m0, __shfl_xor_sync(0xffffffffu, m0, 1));
        m0 = fmaxf(m0, __shfl_xor_sync(0xffffffffu, m0, 2));
        m1 = fmaxf(m1, __shfl_xor_sync(0xffffffffu, m1, 1));
        m1 = fmaxf(m1, __shfl_xor_sync(0xffffffffu, m1, 2));
        float s0 = 0.f, s1 = 0.f;
        #pragma unroll
        for (int j = 0; j < 8; j++) {
            sacc[j][0] = ex2(sacc[j][0] - m0); s0 += sacc[j][0];
            sacc[j][1] = ex2(sacc[j][1] - m0); s0 += sacc[j][1];
            sacc[j][2] = ex2(sacc[j][2] - m1); s1 += sacc[j][2];
            sacc[j][3] = ex2(sacc[j][3] - m1); s1 += sacc[j][3];
        }

        // O = E V (A-fragments repacked from sacc in registers)
        float oacc[4][4];
        #pragma unroll
        for (int j = 0; j < 4; j++)
            #pragma unroll
            for (int e = 0; e < 4; e++) oacc[j][e] = 0.f;

        #pragma unroll
        for (int ks = 0; ks < 4; ks++) {
            uint4 ah, al;
            ah.x = pack2(sacc[2 * ks][0], sacc[2 * ks][1], al.x);
            ah.y = pack2(sacc[2 * ks][2], sacc[2 * ks][3], al.y);
            ah.z = pack2(sacc[2 * ks + 1][0], sacc[2 * ks + 1][1], al.z);
            ah.w = pack2(sacc[2 * ks + 1][2], sacc[2 * ks + 1][3], al.w);
            #pragma unroll
            for (int j = 0; j < 4; j++) {
                uint4 V = sm4[A4_OFF + ks * 1024 + (h * 32 + 8 * j + g) * 4 + t];
                mma3(oacc[j], ah, al, V);
            }
        }

        // normalization sums: off the PV critical path (overlaps mma completion)
        s0 += __shfl_xor_sync(0xffffffffu, s0, 1);
        s0 += __shfl_xor_sync(0xffffffffu, s0, 2);
        s1 += __shfl_xor_sync(0xffffffffu, s1, 1);
        s1 += __shfl_xor_sync(0xffffffffu, s1, 2);
        float inv0 = 1.0f / s0, inv1 = 1.0f / s1;

        // pack O into registers with deferred normalization
        #pragma unroll
        for (int jp = 0; jp < 2; jp++) {
            int j = 2 * jp;
            Ohi[hh][jp * 4 + 0] = pack2(oacc[j][0] * inv0, oacc[j][1] * inv0, Olo[hh][jp * 4 + 0]);
            Ohi[hh][jp * 4 + 1] = pack2(oacc[j][2] * inv1, oacc[j][3] * inv1, Olo[hh][jp * 4 + 1]);
            Ohi[hh][jp * 4 + 2] = pack2(oacc[j + 1][0] * inv0, oacc[j + 1][1] * inv0, Olo[hh][jp * 4 + 2]);
            Ohi[hh][jp * 4 + 3] = pack2(oacc[j + 1][2] * inv1, oacc[j + 1][3] * inv1, Olo[hh][jp * 4 + 3]);
        }
    }
    __syncthreads();   // all K/V smem reads complete

    // ---- write O fragments into smem A region (a4+k4 reused) ----
    #pragma unroll
    for (int hh = 0; hh < 4; hh++) {
        #pragma unroll
        for (int jp = 0; jp < 2; jp++) {
            int kc = (hbase + hh) * 2 + jp;
            int base = kc * 520 + t * 130 + qb * 16;
            sm4[base + g] = make_uint4(Ohi[hh][jp * 4 + 0], Ohi[hh][jp * 4 + 1],
                                       Ohi[hh][jp * 4 + 2], Ohi[hh][jp * 4 + 3]);
            sm4[base + 8 + g] = make_uint4(Olo[hh][jp * 4 + 0], Olo[hh][jp * 4 + 1],
                                           Olo[hh][jp * 4 + 2], Olo[hh][jp * 4 + 3]);
        }
    }
    __syncthreads();   // O fragments visible (O/A region immutable from here)

    // ---- proj phase: out = O @ pw^T + pb ; per-group pipelined slices ----
    const int wmP = (w >> 2) * 32;
    const int wnP = cg * 64;
    const int qB  = (w >> 2) * 2;

    float pacc[2][8][4];
    #pragma unroll
    for (int mt = 0; mt < 2; mt++)
        #pragma unroll
        for (int j = 0; j < 8; j++)
            #pragma unroll
            for (int e = 0; e < 4; e++) pacc[mt][j][e] = 0.f;

    for (int kc = 0; kc < 16; kc++) {
        uint4 Ah[2], Al[2];
        #pragma unroll
        for (int mt = 0; mt < 2; mt++) {
            int ai = kc * 520 + t * 130 + (qB + mt) * 16;
            Ah[mt] = sm4[ai + g];
            Al[mt] = sm4[ai + 8 + g];
        }
        CP_WAIT0();
        barn(1 + cg, 128);
        if (kc + 1 < 16) {
            int Sn = SP0 + ((kc + 1) & 1) * 264;
            #pragma unroll
            for (int k = 0; k < 2; k++) {
                int elem = k * 128 + l128;
                int tt = elem >> 6, q = elem & 63;
                cp16(smem_base + (Sn + tt * 66 + q) * 16,
                     &g_pw4[(kc + 1) * 1024 + tt * 256 + cg * 64 + q]);
            }
            CP_COMMIT();
        }
        int Sc = SP0 + (kc & 1) * 264;
        #pragma unroll
        for (int j = 0; j < 8; j++) {
            uint4 B = sm4[Sc + t * 66 + 8 * j + g];
            mma3(pacc[0][j], Ah[0], Al[0], B);
            mma3(pacc[1][j], Ah[1], Al[1], B);
        }
    }

    // epilogue
    #pragma unroll
    for (int j = 0; j < 8; j++) {
        int oc = wnP + 8 * j + 2 * t;
        float b0 = __ldg(pb + oc), b1 = __ldg(pb + oc + 1);
        #pragma unroll
        for (int mt = 0; mt < 2; mt++) {
            size_t r = (size_t)bw * 128 + wmP + mt * 16 + g;
            *(float2*)(out + r * 256 + oc) =
                make_float2(pacc[mt][j][0] + b0, pacc[mt][j][1] + b1);
            *(float2*)(out + (r + 8) * 256 + oc) =
                make_float2(pacc[mt][j][2] + b0, pacc[mt][j][3] + b1);
        }
    }
}

// ---------------- launch ----------------
static const float* find_by_size(void* const* d_in, const int* in_sizes,
                                 int n_in, int want) {
    for (int i = 0; i < n_in; i++)
        if (in_sizes[i] == want) return (const float*)d_in[i];
    return nullptr;
}

extern "C" void kernel_launch(void* const* d_in, const int* in_sizes, int n_in,
                              void* d_out, int out_size) {
    const float* embeds = find_by_size(d_in, in_sizes, n_in, 128 * 256);
    const float* x      = find_by_size(d_in, in_sizes, n_in, 2 * 256 * 256 * 256);
    const float* rpb    = find_by_size(d_in, in_sizes, n_in, 225 * 8);
    const float* kvw    = find_by_size(d_in, in_sizes, n_in, 512 * 256);
    const float* kvb    = find_by_size(d_in, in_sizes, n_in, 512);
    const float* pw     = find_by_size(d_in, in_sizes, n_in, 256 * 256);
    const float* pb     = find_by_size(d_in, in_sizes, n_in, 256);
    float* out = (float*)d_out;

    prep_all<<<272, 256>>>(embeds, rpb, kvw, pw);

    cudaFuncSetAttribute(win_attn,
                         cudaFuncAttributeMaxDynamicSharedMemorySize, SMEM_BYTES);
    win_attn<<<NWIN, 512, SMEM_BYTES>>>(x, kvb, pb, out);
}

// round 16
// speedup vs baseline: 1.3046x; 1.0594x over previous
#include <cuda_runtime.h>
#include <cuda_bf16.h>
#include <math.h>
#include <stdint.h>

#define DIM 256
#define HEADS 8
#define WIN 64
#define N1 128
#define NWIN 2048
#define SCALE 0.17677669529663687f
#define LOG2E 1.4426950408889634f

// ---------------- device scratch (fragment-packed) ----------------
__device__ uint4 g_q4h[8 * 8 * 2 * 32];          // [h][qb][ks][lane]  (pre-scaled by SCALE*LOG2E)
__device__ uint4 g_q4l[8 * 8 * 2 * 32];
__device__ float4 g_b4[8 * 8 * 8 * 32];          // [h][qb][j][lane]   (pre-scaled by LOG2E)
__device__ uint4 g_kvw4[16 * 4 * 512];           // [kcg][t][n]
__device__ uint4 g_pw4[16 * 4 * 256];            // [kc][t][n]

// ---------------- helpers ----------------
// Fast split+pack: one dual-convert for hi, one for lo. RN rounding identical
// to __float2bfloat16 -> bit-identical results, ~half the instructions.
__device__ __forceinline__ uint32_t pack2(float x0, float x1, uint32_t& lo) {
    uint32_t hi;
    asm("cvt.rn.bf16x2.f32 %0, %1, %2;" : "=r"(hi) : "f"(x1), "f"(x0));
    float h0 = __uint_as_float(hi << 16);
    float h1 = __uint_as_float(hi & 0xffff0000u);
    asm("cvt.rn.bf16x2.f32 %0, %1, %2;" : "=r"(lo) : "f"(x1 - h1), "f"(x0 - h0));
    return hi;
}

// non-volatile mma: lets ptxas software-pipeline LDS->HMMA
__device__ __forceinline__ void mma16(float c[4], uint32_t a0, uint32_t a1,
                                      uint32_t a2, uint32_t a3,
                                      uint32_t b0, uint32_t b1) {
    asm("mma.sync.aligned.m16n8k16.row.col.f32.bf16.bf16.f32 "
        "{%0,%1,%2,%3},{%4,%5,%6,%7},{%8,%9},{%0,%1,%2,%3};\n"
        : "+f"(c[0]), "+f"(c[1]), "+f"(c[2]), "+f"(c[3])
        : "r"(a0), "r"(a1), "r"(a2), "r"(a3), "r"(b0), "r"(b1));
}
__device__ __forceinline__ void mma3(float c[4], const uint4& ah, const uint4& al,
                                     const uint4& B) {
    mma16(c, ah.x, ah.y, ah.z, ah.w, B.x, B.y);
    mma16(c, ah.x, ah.y, ah.z, ah.w, B.z, B.w);
    mma16(c, al.x, al.y, al.z, al.w, B.x, B.y);
}

__device__ __forceinline__ float ex2(float x) {
    float r;
    asm("ex2.approx.f32 %0, %1;" : "=f"(r) : "f"(x));
    return r;
}

__device__ __forceinline__ void cp16(uint32_t dst_smem, const void* src) {
    asm volatile("cp.async.cg.shared.global [%0], [%1], 16;\n"
                 :: "r"(dst_smem), "l"(src));
}
#define CP_COMMIT() asm volatile("cp.async.commit_group;\n")
#define CP_WAIT0()  asm volatile("cp.async.wait_group 0;\n")

__device__ __forceinline__ void barn(int id, int cnt) {
    asm volatile("bar.sync %0, %1;" :: "r"(id), "r"(cnt) : "memory");
}

// bias formula (relative position)
__device__ __forceinline__ float bias_val(const float* rpb, int h, int r, int k) {
    int i1 = r >> 3, j1 = r & 7, i2 = k >> 3, j2 = k & 7;
    int idx = (i1 - i2 + 7) * 15 + (j1 - j2 + 7);
    return rpb[idx * HEADS + h];
}

// ---------------- merged prep kernel ----------------
__global__ void prep_all(const float* __restrict__ e, const float* __restrict__ rpb,
                         const float* __restrict__ kvw, const float* __restrict__ pw) {
    int gi = blockIdx.x * blockDim.x + threadIdx.x;
    if (gi < 4096) {
        int i = gi;
        int lane = i & 31, ks = (i >> 5) & 1, qb = (i >> 6) & 7, h = i >> 9;
        int g = lane >> 2, t = lane & 3;
        int q0 = qb * 16 + g;
        const float QS = SCALE * LOG2E;
        uint4 hi, lo;
        int d0 = h * 32 + (8 * ks + t) * 2;
        int d1 = h * 32 + (8 * ks + t + 4) * 2;
        hi.x = pack2(e[q0 * DIM + d0] * QS, e[q0 * DIM + d0 + 1] * QS, lo.x);
        hi.y = pack2(e[(q0 + 8) * DIM + d0] * QS, e[(q0 + 8) * DIM + d0 + 1] * QS, lo.y);
        hi.z = pack2(e[q0 * DIM + d1] * QS, e[q0 * DIM + d1 + 1] * QS, lo.z);
        hi.w = pack2(e[(q0 + 8) * DIM + d1] * QS, e[(q0 + 8) * DIM + d1 + 1] * QS, lo.w);
        g_q4h[i] = hi; g_q4l[i] = lo;
    } else if (gi < 4096 + 16384) {
        int i = gi - 4096;
        int lane = i & 31, j = (i >> 5) & 7, qb = (i >> 8) & 7, h = i >> 11;
        int g = lane >> 2, t = lane & 3;
        int r0 = (qb * 16 + g) & 63, r1 = (qb * 16 + g + 8) & 63;
        int c = 8 * j + 2 * t;
        float4 v;
        v.x = bias_val(rpb, h, r0, c) * LOG2E;
        v.y = bias_val(rpb, h, r0, c + 1) * LOG2E;
        v.z = bias_val(rpb, h, r1, c) * LOG2E;
        v.w = bias_val(rpb, h, r1, c + 1) * LOG2E;
        g_b4[i] = v;
    } else if (gi < 4096 + 16384 + 32768) {
        int i = gi - 20480;
        int n = i & 511, t = (i >> 9) & 3, kcg = i >> 11;   // 0..15
        int kwA = kcg * 8 + t, kwB = kwA + 4;
        uint4 v;
        v.x = pack2(kvw[n * 256 + 2 * kwA], kvw[n * 256 + 2 * kwA + 1], v.z);
        v.y = pack2(kvw[n * 256 + 2 * kwB], kvw[n * 256 + 2 * kwB + 1], v.w);
        g_kvw4[i] = v;
    } else if (gi < 4096 + 16384 + 32768 + 16384) {
        int ii = gi - 53248;
        int n = ii & 255, t = (ii >> 8) & 3, kc = ii >> 10;  // 0..15
        int kwA = kc * 8 + t, kwB = kwA + 4;
        uint4 v;
        v.x = pack2(pw[n * 256 + 2 * kwA], pw[n * 256 + 2 * kwA + 1], v.z);
        v.y = pack2(pw[n * 256 + 2 * kwB], pw[n * 256 + 2 * kwB + 1], v.w);
        g_pw4[ii] = v;
    }
}

// ---------------- fused window kernel (KV GEMM + attention + proj) -----------
// smem layout identical to R13/R14
#define A4_OFF  0
#define K4_OFF  4352
#define WS4_OFF 8704
#define SMEM_BYTES 208896

extern __shared__ uint4 sm4[];

__global__ __launch_bounds__(512, 1)
void win_attn(const float* __restrict__ x, const float* __restrict__ kvb,
              const float* __restrict__ pb, float* __restrict__ out) {
    const int tid  = threadIdx.x;
    const int bw   = blockIdx.x;
    const int b    = bw >> 10;
    const int wr   = (bw >> 5) & 31;
    const int wc   = bw & 31;
    const int w    = tid >> 5;
    const int lane = tid & 31;
    const int g    = lane >> 2;
    const int t    = lane & 3;
    float* kvbf = (float*)(sm4 + 12928);
    uint32_t* a4w = (uint32_t*)sm4;
    uint32_t smem_base;
    asm("{ .reg .u64 tmp; cvta.to.shared.u64 tmp, %1; cvt.u32.u64 %0, tmp; }"
        : "=r"(smem_base) : "l"((void*)sm4));

    // slice-group ids
    const int p    = w & 7;              // KV pair id (warps {p, p+8})
    const int sub  = w >> 3;
    const int q32  = lane + sub * 32;
    const int SKV0 = WS4_OFF + p * 528;

    // ---- KV prologue: each pair stages its kcg0 slice ----
    #pragma unroll
    for (int k = 0; k < 4; k++)
        cp16(smem_base + (SKV0 + k * 66 + q32) * 16,
             &g_kvw4[k * 512 + p * 64 + q32]);
    CP_COMMIT();

    // ---- load window tile, split+pack, scatter into a4 fragment layout ----
    {
        const float4* xv = (const float4*)(x +
            ((size_t)((b * 256 + wr * 8) * 256 + wc * 8)) * 256);
        #pragma unroll
        for (int i = 0; i < 8; i++) {
            int idx = tid + i * 512;
            int tok = idx >> 6, c4 = idx & 63;
            int r = tok >> 3, cc = tok & 7;
            float4 v = xv[r * 16384 + cc * 64 + c4];
            int m = tok >> 4, gg = tok & 15;
            int g2 = gg & 7, r8 = gg >> 3;
            int kcg = c4 >> 2, rem = c4 & 3;
            uint32_t lo0, lo1;
            uint32_t hi0 = pack2(v.x, v.y, lo0);
            uint32_t hi1 = pack2(v.z, v.w, lo1);
            int tt0 = 2 * rem, tt1 = tt0 + 1;
            int i0 = kcg * 136 + (tt0 & 3) * 34 + m * 8 + g2;
            int w0 = r8 + 2 * (tt0 >> 2);
            a4w[i0 * 4 + w0] = hi0;
            a4w[(i0 + 2176) * 4 + w0] = lo0;
            int i1 = kcg * 136 + (tt1 & 3) * 34 + m * 8 + g2;
            int w1 = r8 + 2 * (tt1 >> 2);
            a4w[i1 * 4 + w1] = hi1;
            a4w[(i1 + 2176) * 4 + w1] = lo1;
        }
        kvbf[tid] = kvb[tid];
    }
    __syncthreads();   // a4 (A fragments) + kvbf stable and visible from here

    // ---- KV GEMM: per-pair pipelined slices; NO CTA barriers in loop ----
    const int wmK = (w >> 3) * 32;
    const int wnK = p * 64;
    const int mB  = (w >> 3) * 2;

    float acc[2][8][4];
    #pragma unroll
    for (int mt = 0; mt < 2; mt++)
        #pragma unroll
        for (int j = 0; j < 8; j++)
            #pragma unroll
            for (int e = 0; e < 4; e++) acc[mt][j][e] = 0.f;

    for (int kcg = 0; kcg < 16; kcg++) {
        uint4 Ah[2], Al[2];
        #pragma unroll
        for (int mt = 0; mt < 2; mt++) {
            int ai = A4_OFF + kcg * 136 + t * 34 + (mB + mt) * 8 + g;
            Ah[mt] = sm4[ai];
            Al[mt] = sm4[ai + 2176];
        }
        CP_WAIT0();
        barn(1 + p, 64);
        if (kcg + 1 < 16) {
            int Sn = SKV0 + ((kcg + 1) & 1) * 264;
            #pragma unroll
            for (int k = 0; k < 4; k++)
                cp16(smem_base + (Sn + k * 66 + q32) * 16,
                     &g_kvw4[(kcg + 1) * 2048 + k * 512 + p * 64 + q32]);
            CP_COMMIT();
        }
        int Sc = SKV0 + (kcg & 1) * 264;
        #pragma unroll
        for (int j = 0; j < 8; j++) {
            uint4 B = sm4[Sc + t * 66 + 8 * j + g];
            mma3(acc[0][j], Ah[0], Al[0], B);
            mma3(acc[1][j], Ah[1], Al[1], B);
        }
    }
    __syncthreads();   // all a4 + ws4 reads done (V will alias a4; proj reuses ws4)

    // ---- proj kc=0 slice prologue: issue NOW, lands during attention ----
    const int cg   = w & 3;
    const int l128 = (w >> 2) * 32 + lane;
    const int SP0  = WS4_OFF + cg * 528;
    #pragma unroll
    for (int k = 0; k < 2; k++) {
        int elem = k * 128 + l128;
        int tt = elem >> 6, q = elem & 63;
        cp16(smem_base + (SP0 + tt * 66 + q) * 16,
             &g_pw4[tt * 256 + cg * 64 + q]);
    }
    CP_COMMIT();

    // ---- epilogues: K warps (wnK<256) -> k4 ; V warps -> a4 alias ----
    if (wnK < 256) {
        #pragma unroll
        for (int mt = 0; mt < 2; mt++) {
            int key0 = wmK + mt * 16 + g;
            #pragma unroll
            for (int jp = 0; jp < 4; jp++) {
                int j = 2 * jp;
                int c  = wnK + 8 * j + 2 * t;
                int c2 = c + 8;
                float b0 = kvbf[c], b1 = kvbf[c + 1];
                float b2 = kvbf[c2], b3 = kvbf[c2 + 1];
                int G = (wnK >> 4) + jp;
                uint4 u;
                u.x = pack2(acc[mt][j][0] + b0, acc[mt][j][1] + b1, u.z);
                u.y = pack2(acc[mt][j + 1][0] + b2, acc[mt][j + 1][1] + b3, u.w);
                sm4[K4_OFF + key0 * 68 + G * 4 + t] = u;
                uint4 v;
                v.x = pack2(acc[mt][j][2] + b0, acc[mt][j][3] + b1, v.z);
                v.y = pack2(acc[mt][j + 1][2] + b2, acc[mt][j + 1][3] + b3, v.w);
                sm4[K4_OFF + (key0 + 8) * 68 + G * 4 + t] = v;
            }
        }
    } else {
        #pragma unroll
        for (int mt = 0; mt < 2; mt++) {
            int ks = mB + mt;
            #pragma unroll
            for (int j = 0; j < 8; j++) {
                int c = wnK - 256 + 8 * j + 2 * t;
                float b0 = kvbf[256 + c], b1 = kvbf[256 + c + 1];
                float v0 = acc[mt][j][0] + b0, v1 = acc[mt][j][1] + b1;
                float v2 = acc[mt][j][2] + b0, v3 = acc[mt][j][3] + b1;
                float o0 = __shfl_xor_sync(0xffffffffu, v0, 4);
                float o1 = __shfl_xor_sync(0xffffffffu, v1, 4);
                float o2 = __shfl_xor_sync(0xffffffffu, v2, 4);
                float o3 = __shfl_xor_sync(0xffffffffu, v3, 4);
                if ((g & 1) == 0) {
                    int tq = g >> 1;
                    uint4 u;
                    u.x = pack2(v0, o0, u.z);
                    u.y = pack2(v2, o2, u.w);
                    sm4[A4_OFF + ks * 1024 + c * 4 + tq] = u;
                    uint4 v;
                    v.x = pack2(v1, o1, v.z);
                    v.y = pack2(v3, o3, v.w);
                    sm4[A4_OFF + ks * 1024 + (c + 1) * 4 + tq] = v;
                }
            }
        }
    }
    __syncthreads();

    // ---- attention: 16 warps = 8 q-blocks x 2 head-groups; O kept in regs ----
    const int qb = w >> 1;
    const int hbase = (w & 1) * 4;
    uint32_t Ohi[4][8], Olo[4][8];

    #pragma unroll
    for (int hh = 0; hh < 4; hh++) {
        const int h = hbase + hh;

        float sacc[8][4];
        #pragma unroll
        for (int j = 0; j < 8; j++) {
            float4 bv = __ldg(&g_b4[((h * 8 + qb) * 8 + j) * 32 + lane]);
            sacc[j][0] = bv.x; sacc[j][1] = bv.y;
            sacc[j][2] = bv.z; sacc[j][3] = bv.w;
        }
        #pragma unroll
        for (int ks = 0; ks < 2; ks++) {
            uint4 Qh = __ldg(&g_q4h[((h * 8 + qb) * 2 + ks) * 32 + lane]);
            uint4 Ql = __ldg(&g_q4l[((h * 8 + qb) * 2 + ks) * 32 + lane]);
            #pragma unroll
            for (int j = 0; j < 8; j++) {
                uint4 K = sm4[K4_OFF + (8 * j + g) * 68 + (h * 2 + ks) * 4 + t];
                mma3(sacc[j], Qh, Ql, K);
            }
        }

        // softmax (base-2 domain); E unnormalized
        float m0 = -1e30f, m1 = -1e30f;
        #pragma unroll
        for (int j = 0; j < 8; j++) {
            m0 = fmaxf(m0, fmaxf(sacc[j][0], sacc[j][1]));
            m1 = fmaxf(m1, fmaxf(sacc[j][2], sacc[j][3]));
        }
        m0 = fmaxf(m0, __shfl_xor_sync(0xffffffffu, m0, 1));
        m0 = fmaxf(m0, __shfl_xor_sync(0xffffffffu, m0, 2));
        m1 = fmaxf(m1, __shfl_xor_sync(0xffffffffu, m1, 1));
        m1 = fmaxf(m1, __shfl_xor_sync(0xffffffffu, m1, 2));
        float s0 = 0.f, s1 = 0.f;
        #pragma unroll
        for (int j = 0; j < 8; j++) {
            sacc[j][0] = ex2(sacc[j][0] - m0); s0 += sacc[j][0];
            sacc[j][1] = ex2(sacc[j][1] - m0); s0 += sacc[j][1];
            sacc[j][2] = ex2(sacc[j][2] - m1); s1 += sacc[j][2];
            sacc[j][3] = ex2(sacc[j][3] - m1); s1 += sacc[j][3];
        }

        // O = E V (A-fragments repacked from sacc in registers)
        float oacc[4][4];
        #pragma unroll
        for (int j = 0; j < 4; j++)
            #pragma unroll
            for (int e = 0; e < 4; e++) oacc[j][e] = 0.f;

        #pragma unroll
        for (int ks = 0; ks < 4; ks++) {
            uint4 ah, al;
            ah.x = pack2(sacc[2 * ks][0], sacc[2 * ks][1], al.x);
            ah.y = pack2(sacc[2 * ks][2], sacc[2 * ks][3], al.y);
            ah.z = pack2(sacc[2 * ks + 1][0], sacc[2 * ks + 1][1], al.z);
            ah.w = pack2(sacc[2 * ks + 1][2], sacc[2 * ks + 1][3], al.w);
            #pragma unroll
            for (int j = 0; j < 4; j++) {
                uint4 V = sm4[A4_OFF + ks * 1024 + (h * 32 + 8 * j + g) * 4 + t];
                mma3(oacc[j], ah, al, V);
            }
        }

        // normalization sums: off the PV critical path
        s0 += __shfl_xor_sync(0xffffffffu, s0, 1);
        s0 += __shfl_xor_sync(0xffffffffu, s0, 2);
        s1 += __shfl_xor_sync(0xffffffffu, s1, 1);
        s1 += __shfl_xor_sync(0xffffffffu, s1, 2);
        float inv0 = 1.0f / s0, inv1 = 1.0f / s1;

        // pack O into registers with deferred normalization
        #pragma unroll
        for (int jp = 0; jp < 2; jp++) {
            int j = 2 * jp;
            Ohi[hh][jp * 4 + 0] = pack2(oacc[j][0] * inv0, oacc[j][1] * inv0, Olo[hh][jp * 4 + 0]);
            Ohi[hh][jp * 4 + 1] = pack2(oacc[j][2] * inv1, oacc[j][3] * inv1, Olo[hh][jp * 4 + 1]);
            Ohi[hh][jp * 4 + 2] = pack2(oacc[j + 1][0] * inv0, oacc[j + 1][1] * inv0, Olo[hh][jp * 4 + 2]);
            Ohi[hh][jp * 4 + 3] = pack2(oacc[j + 1][2] * inv1, oacc[j + 1][3] * inv1, Olo[hh][jp * 4 + 3]);
        }
    }
    __syncthreads();   // all K/V smem reads complete

    // ---- write O fragments into smem A region (a4+k4 reused) ----
    #pragma unroll
    for (int hh = 0; hh < 4; hh++) {
        #pragma unroll
        for (int jp = 0; jp < 2; jp++) {
            int kc = (hbase + hh) * 2 + jp;
            int base = kc * 520 + t * 130 + qb * 16;
            sm4[base + g] = make_uint4(Ohi[hh][jp * 4 + 0], Ohi[hh][jp * 4 + 1],
                                       Ohi[hh][jp * 4 + 2], Ohi[hh][jp * 4 + 3]);
            sm4[base + 8 + g] = make_uint4(Olo[hh][jp * 4 + 0], Olo[hh][jp * 4 + 1],
                                           Olo[hh][jp * 4 + 2], Olo[hh][jp * 4 + 3]);
        }
    }
    __syncthreads();   // O fragments visible (O/A region immutable from here)

    // ---- proj phase: out = O @ pw^T + pb ; per-group pipelined slices ----
    const int wmP = (w >> 2) * 32;
    const int wnP = cg * 64;
    const int qB  = (w >> 2) * 2;

    float pacc[2][8][4];
    #pragma unroll
    for (int mt = 0; mt < 2; mt++)
        #pragma unroll
        for (int j = 0; j < 8; j++)
            #pragma unroll
            for (int e = 0; e < 4; e++) pacc[mt][j][e] = 0.f;

    for (int kc = 0; kc < 16; kc++) {
        uint4 Ah[2], Al[2];
        #pragma unroll
        for (int mt = 0; mt < 2; mt++) {
            int ai = kc * 520 + t * 130 + (qB + mt) * 16;
            Ah[mt] = sm4[ai + g];
            Al[mt] = sm4[ai + 8 + g];
        }
        CP_WAIT0();
        barn(1 + cg, 128);
        if (kc + 1 < 16) {
            int Sn = SP0 + ((kc + 1) & 1) * 264;
            #pragma unroll
            for (int k = 0; k < 2; k++) {
                int elem = k * 128 + l128;
                int tt = elem >> 6, q = elem & 63;
                cp16(smem_base + (Sn + tt * 66 + q) * 16,
                     &g_pw4[(kc + 1) * 1024 + tt * 256 + cg * 64 + q]);
            }
            CP_COMMIT();
        }
        int Sc = SP0 + (kc & 1) * 264;
        #pragma unroll
        for (int j = 0; j < 8; j++) {
            uint4 B = sm4[Sc + t * 66 + 8 * j + g];
            mma3(pacc[0][j], Ah[0], Al[0], B);
            mma3(pacc[1][j], Ah[1], Al[1], B);
        }
    }

    // epilogue
    #pragma unroll
    for (int j = 0; j < 8; j++) {
        int oc = wnP + 8 * j + 2 * t;
        float b0 = __ldg(pb + oc), b1 = __ldg(pb + oc + 1);
        #pragma unroll
        for (int mt = 0; mt < 2; mt++) {
            size_t r = (size_t)bw * 128 + wmP + mt * 16 + g;
            *(float2*)(out + r * 256 + oc) =
                make_float2(pacc[mt][j][0] + b0, pacc[mt][j][1] + b1);
            *(float2*)(out + (r + 8) * 256 + oc) =
                make_float2(pacc[mt][j][2] + b0, pacc[mt][j][3] + b1);
        }
    }
}

// ---------------- launch ----------------
static const float* find_by_size(void* const* d_in, const int* in_sizes,
                                 int n_in, int want) {
    for (int i = 0; i < n_in; i++)
        if (in_sizes[i] == want) return (const float*)d_in[i];
    return nullptr;
}

extern "C" void kernel_launch(void* const* d_in, const int* in_sizes, int n_in,
                              void* d_out, int out_size) {
    const float* embeds = find_by_size(d_in, in_sizes, n_in, 128 * 256);
    const float* x      = find_by_size(d_in, in_sizes, n_in, 2 * 256 * 256 * 256);
    const float* rpb    = find_by_size(d_in, in_sizes, n_in, 225 * 8);
    const float* kvw    = find_by_size(d_in, in_sizes, n_in, 512 * 256);
    const float* kvb    = find_by_size(d_in, in_sizes, n_in, 512);
    const float* pw     = find_by_size(d_in, in_sizes, n_in, 256 * 256);
    const float* pb     = find_by_size(d_in, in_sizes, n_in, 256);
    float* out = (float*)d_out;

    prep_all<<<272, 256>>>(embeds, rpb, kvw, pw);

    cudaFuncSetAttribute(win_attn,
                         cudaFuncAttributeMaxDynamicSharedMemorySize, SMEM_BYTES);
    win_attn<<<NWIN, 512, SMEM_BYTES>>>(x, kvb, pb, out);
}